// round 2
// baseline (speedup 1.0000x reference)
#include <cuda_runtime.h>
#include <cuda_bf16.h>

#define BB 4
#define NN 261888
#define PP 6000
#define NP 2000
#define NBINS 65536
#define CAP 16384
#define NW 94          // ceil(PP/64)
#define NWPAD 96       // padded row (16B aligned)
#define NSEG 64
#define SEGCAP 4096

typedef unsigned long long u64;

// ---------------- scratch (device globals; no allocations) ----------------
__device__ unsigned int        g_hist[BB][NBINS];
__device__ unsigned int        g_cursor[BB][NBINS];
__device__ int                 g_thresh[BB];
__device__ u64                 g_cand[BB][CAP];
__device__ __align__(16) float4 g_boxes[BB][PP];
__device__ float               g_area[BB][PP];
__device__ __align__(16) u64   g_supp[BB][PP][NWPAD];

// ---------------- K0: zero histogram + thresholds ----------------
__global__ void k_zero() {
    int gid = blockIdx.x * blockDim.x + threadIdx.x;
    if (gid < BB * NBINS) ((unsigned int*)g_hist)[gid] = 0u;
    if (gid < BB) g_thresh[gid] = NBINS;
}

// ---------------- K1: histogram over top-16 bits of score ----------------
__global__ void k_hist(const float* __restrict__ rpn_class) {
    int i = blockIdx.x * blockDim.x + threadIdx.x;
    int b = blockIdx.y;
    if (i >= NN) return;
    float2 sc = *(const float2*)(rpn_class + ((size_t)b * NN + i) * 2);
    unsigned bits = __float_as_uint(sc.y);   // score in [0,1): bits order-preserving
    atomicAdd(&g_hist[b][bits >> 16], 1u);
}

// ---------------- K2: descending exclusive prefix sum; find threshold ----------------
__global__ void k_scan() {
    int b = blockIdx.x, t = threadIdx.x;
    __shared__ unsigned gs[1024];
    unsigned s = 0;
    #pragma unroll 8
    for (int k = 0; k < 64; k++) s += g_hist[b][t * 64 + k];
    gs[t] = s;
    __syncthreads();
    unsigned self = s;
    for (int off = 1; off < 1024; off <<= 1) {
        unsigned v = (t + off < 1024) ? gs[t + off] : 0u;
        __syncthreads();
        gs[t] += v;
        __syncthreads();
    }
    unsigned run = gs[t] - self;
    int minbin = NBINS;
    for (int k = 63; k >= 0; k--) {
        int bin = t * 64 + k;
        g_cursor[b][bin] = run;
        if (run < PP) minbin = bin;
        run += g_hist[b][bin];
    }
    if (minbin < NBINS) atomicMin(&g_thresh[b], minbin);
}

// ---------------- K3: scatter candidates grouped by bin ----------------
__global__ void k_scatter(const float* __restrict__ rpn_class) {
    int i = blockIdx.x * blockDim.x + threadIdx.x;
    int b = blockIdx.y;
    if (i >= NN) return;
    float2 sc = *(const float2*)(rpn_class + ((size_t)b * NN + i) * 2);
    unsigned bits = __float_as_uint(sc.y);
    int bin = bits >> 16;
    if (bin >= g_thresh[b]) {
        unsigned pos = atomicAdd(&g_cursor[b][bin], 1u);
        if (pos < CAP) {
            g_cand[b][pos] = ((u64)bits << 32)
                           | (u64)(0xFFFFFFFFu - (unsigned)i);
        }
    }
}

// ---------------- K4: bitonic sort each bin segment (descending) ----------------
__global__ void k_segsort() {
    int b = blockIdx.y;
    int bin = g_thresh[b] + blockIdx.x;
    if (bin >= NBINS) return;
    unsigned cnt = g_hist[b][bin];
    if (cnt <= 1) return;
    unsigned base = g_cursor[b][bin] - cnt;
    __shared__ u64 key[SEGCAP];
    unsigned cc = cnt < (unsigned)SEGCAP ? cnt : (unsigned)SEGCAP;
    unsigned m = 2; while (m < cc) m <<= 1;
    for (unsigned x = threadIdx.x; x < m; x += blockDim.x)
        key[x] = (x < cc) ? g_cand[b][base + x] : 0ull;
    __syncthreads();
    for (unsigned k = 2; k <= m; k <<= 1) {
        for (unsigned j = k >> 1; j > 0; j >>= 1) {
            for (unsigned x = threadIdx.x; x < m; x += blockDim.x) {
                unsigned l = x ^ j;
                if (l > x) {
                    u64 a = key[x], c = key[l];
                    bool up = ((x & k) == 0);
                    if (up ? (a < c) : (a > c)) { key[x] = c; key[l] = a; }
                }
            }
            __syncthreads();
        }
    }
    for (unsigned x = threadIdx.x; x < cc; x += blockDim.x)
        g_cand[b][base + x] = key[x];
}

// ---------------- K5: decode, clip, normalize top-P boxes ----------------
__global__ void k_decode(const float* __restrict__ rpn_bbox,
                         const float* __restrict__ anchors) {
    int p = blockIdx.x * blockDim.x + threadIdx.x;
    int b = blockIdx.y;
    if (p >= PP) return;
    u64 key = g_cand[b][p];
    unsigned idx = 0xFFFFFFFFu - (unsigned)(key & 0xFFFFFFFFull);
    float4 a = *(const float4*)(anchors + (size_t)idx * 4);
    float4 d = *(const float4*)(rpn_bbox + ((size_t)b * NN + idx) * 4);
    d.x *= 0.1f; d.y *= 0.1f; d.z *= 0.2f; d.w *= 0.2f;
    float h = a.z - a.x, w = a.w - a.y;
    float cy = a.x + 0.5f * h, cx = a.y + 0.5f * w;
    cy = cy + d.x * h;
    cx = cx + d.y * w;
    h = h * expf(d.z);
    w = w * expf(d.w);
    float y1 = cy - 0.5f * h, x1 = cx - 0.5f * w;
    float y2 = cy + 0.5f * h, x2 = cx + 0.5f * w;
    y1 = fminf(fmaxf(y1, 0.f), 1024.f);
    x1 = fminf(fmaxf(x1, 0.f), 1024.f);
    y2 = fminf(fmaxf(y2, 0.f), 1024.f);
    x2 = fminf(fmaxf(x2, 0.f), 1024.f);
    const float inv = 1.0f / 1024.0f;
    float4 o = make_float4(y1 * inv, x1 * inv, y2 * inv, x2 * inv);
    g_boxes[b][p] = o;
    g_area[b][p] = (o.z - o.x) * (o.w - o.y);
}

// ---------------- K6: suppression bitmask matrix (upper triangle only) ----------------
__global__ void k_mask() {
    int jb = blockIdx.x, ib = blockIdx.y, b = blockIdx.z;
    if (jb < ib) return;                 // lower triangle never read by new k_nms
    int tid = threadIdx.x;
    int i = ib * 64 + tid;
    __shared__ float4 bj[64];
    __shared__ float  aj[64];
    int j0 = jb * 64;
    int jt = j0 + tid;
    if (jt < PP) { bj[tid] = g_boxes[b][jt]; aj[tid] = g_area[b][jt]; }
    __syncthreads();
    if (i >= PP) return;
    float4 bi = g_boxes[b][i];
    float  ai = g_area[b][i];
    u64 mask = 0ull;
    int jmax = min(64, PP - j0);
    #pragma unroll 4
    for (int jj = 0; jj < jmax; jj++) {
        int j = j0 + jj;
        if (j <= i) continue;
        float4 bx = bj[jj];
        float iy1 = fmaxf(bi.x, bx.x), ix1 = fmaxf(bi.y, bx.y);
        float iy2 = fminf(bi.z, bx.z), ix2 = fminf(bi.w, bx.w);
        float ih = fmaxf(iy2 - iy1, 0.f), iw = fmaxf(ix2 - ix1, 0.f);
        float inter = ih * iw;
        float uni = ai + aj[jj] - inter;
        if (inter > 0.7f * fmaxf(uni, 1e-8f)) mask |= (1ull << jj);
    }
    g_supp[b][i][jb] = mask;
}

// ---------------- K7: blocked greedy NMS, 64 candidates per step ----------------
// Thread t (<NW) keeps the running "removed" word t in a register.
// Per 64-block: ballot nonzero-diag rows (sparse!), resolve serially only over
// those, truncate at NP kept, then all threads OR kept rows into their word.
__global__ void k_nms(float* __restrict__ out) {
    int b = blockIdx.x, tid = threadIdx.x;
    __shared__ u64 diag[2][64];
    __shared__ u64 sm_pre, sm_kept;
    __shared__ unsigned sm_nz[2];
    __shared__ int sm_base, sm_prev, sm_stop;

    float4* ob = (float4*)(out + (size_t)b * NP * 4);
    for (int x = tid; x < NP; x += blockDim.x) ob[x] = make_float4(0.f, 0.f, 0.f, 0.f);

    u64 acc = 0ull;  // removed word `tid`
    if (tid == 0) { sm_base = 0; sm_stop = 0; }
    if (tid < 64) diag[0][tid] = g_supp[b][tid][0];   // diag block 0
    __syncthreads();

    for (int blk = 0; blk < NW; blk++) {
        int buf = blk & 1;
        if (tid == blk) sm_pre = acc;
        if (tid < 64) {
            u64 d = diag[buf][tid];
            unsigned bal = __ballot_sync(0xffffffffu, d != 0ull);
            if ((tid & 31) == 0) sm_nz[tid >> 5] = bal;
        } else if (blk + 1 < NW) {
            int j = tid - 64, row = (blk + 1) * 64 + j;
            diag[buf ^ 1][j] = (row < PP) ? g_supp[b][row][blk + 1] : 0ull;
        }
        __syncthreads();

        if (tid == 0) {
            u64 jm = (u64)sm_nz[0] | ((u64)sm_nz[1] << 32);
            u64 alive = ~sm_pre;
            if (blk == NW - 1) alive &= (1ull << (PP - (NW - 1) * 64)) - 1ull;
            while (jm) {
                int j = __ffsll((long long)jm) - 1; jm &= jm - 1;
                if ((alive >> j) & 1ull) alive &= ~diag[buf][j];
            }
            int cnt = __popcll(alive);
            int rem = NP - sm_base;
            while (cnt > rem) {  // truncate: drop highest-index kept bits
                alive &= ~(1ull << (63 - __clzll((long long)alive)));
                cnt--;
            }
            sm_kept = alive;
            sm_prev = sm_base;
            sm_base += cnt;
            if (sm_base >= NP) sm_stop = 1;
        }
        __syncthreads();

        u64 km = sm_kept;
        if (tid < 64 && ((km >> tid) & 1ull)) {
            u64 lowmask = (tid == 0) ? 0ull : (km & ((1ull << tid) - 1ull));
            int rank = sm_prev + __popcll(lowmask);
            ob[rank] = g_boxes[b][blk * 64 + tid];
        }
        if (tid < NW && tid > blk) {
            u64 t = km;
            while (t) {
                int j = __ffsll((long long)t) - 1; t &= t - 1;
                acc |= g_supp[b][blk * 64 + j][tid];
            }
        }
        __syncthreads();
        if (sm_stop) break;
    }
}

// ---------------- launch ----------------
extern "C" void kernel_launch(void* const* d_in, const int* in_sizes, int n_in,
                              void* d_out, int out_size) {
    const float* rpn_class = (const float*)d_in[0];
    const float* rpn_bbox  = (const float*)d_in[1];
    const float* anchors   = (const float*)d_in[2];
    float* out = (float*)d_out;

    k_zero<<<(BB * NBINS + 1023) / 1024, 1024>>>();
    dim3 ghist((NN + 255) / 256, BB);
    k_hist<<<ghist, 256>>>(rpn_class);
    k_scan<<<BB, 1024>>>();
    k_scatter<<<ghist, 256>>>(rpn_class);
    k_segsort<<<dim3(NSEG, BB), 256>>>();
    k_decode<<<dim3((PP + 127) / 128, BB), 128>>>(rpn_bbox, anchors);
    k_mask<<<dim3(NW, NW, BB), 64>>>();
    k_nms<<<BB, 128>>>(out);
}

// round 3
// speedup vs baseline: 2.0310x; 2.0310x over previous
#include <cuda_runtime.h>
#include <cuda_bf16.h>

#define BB 4
#define NN 261888
#define PP 6000
#define NP 2000
#define NBINS 65536
#define CAP 16384
#define NW 94          // ceil(PP/64)
#define NWPAD 96       // padded row (16B aligned)
#define NSEG 64
#define SEGCAP 4096

typedef unsigned long long u64;

// ---------------- scratch (device globals; no allocations) ----------------
__device__ unsigned int        g_hist[BB][NBINS];
__device__ unsigned int        g_cursor[BB][NBINS];
__device__ int                 g_thresh[BB];
__device__ u64                 g_cand[BB][CAP];
__device__ __align__(16) float4 g_boxes[BB][PP];
__device__ float               g_area[BB][PP];
__device__ __align__(16) u64   g_supp[BB][PP][NWPAD];
__device__ __align__(16) u64   g_diag[BB][PP];

// ---------------- K0: zero histogram + thresholds ----------------
__global__ void k_zero() {
    int gid = blockIdx.x * blockDim.x + threadIdx.x;
    if (gid < BB * NBINS) ((unsigned int*)g_hist)[gid] = 0u;
    if (gid < BB) g_thresh[gid] = NBINS;
}

// ---------------- K1: histogram over top-16 bits of score ----------------
__global__ void k_hist(const float* __restrict__ rpn_class) {
    int i = blockIdx.x * blockDim.x + threadIdx.x;
    int b = blockIdx.y;
    if (i >= NN) return;
    float2 sc = *(const float2*)(rpn_class + ((size_t)b * NN + i) * 2);
    unsigned bits = __float_as_uint(sc.y);   // score in [0,1): bits order-preserving
    atomicAdd(&g_hist[b][bits >> 16], 1u);
}

// ---------------- K2: descending exclusive prefix sum; find threshold ----------------
__global__ void k_scan() {
    int b = blockIdx.x, t = threadIdx.x;
    __shared__ unsigned gs[1024];
    unsigned s = 0;
    #pragma unroll 8
    for (int k = 0; k < 64; k++) s += g_hist[b][t * 64 + k];
    gs[t] = s;
    __syncthreads();
    unsigned self = s;
    for (int off = 1; off < 1024; off <<= 1) {
        unsigned v = (t + off < 1024) ? gs[t + off] : 0u;
        __syncthreads();
        gs[t] += v;
        __syncthreads();
    }
    unsigned run = gs[t] - self;
    int minbin = NBINS;
    for (int k = 63; k >= 0; k--) {
        int bin = t * 64 + k;
        g_cursor[b][bin] = run;
        if (run < PP) minbin = bin;
        run += g_hist[b][bin];
    }
    if (minbin < NBINS) atomicMin(&g_thresh[b], minbin);
}

// ---------------- K3: scatter candidates grouped by bin ----------------
__global__ void k_scatter(const float* __restrict__ rpn_class) {
    int i = blockIdx.x * blockDim.x + threadIdx.x;
    int b = blockIdx.y;
    if (i >= NN) return;
    float2 sc = *(const float2*)(rpn_class + ((size_t)b * NN + i) * 2);
    unsigned bits = __float_as_uint(sc.y);
    int bin = bits >> 16;
    if (bin >= g_thresh[b]) {
        unsigned pos = atomicAdd(&g_cursor[b][bin], 1u);
        if (pos < CAP) {
            g_cand[b][pos] = ((u64)bits << 32)
                           | (u64)(0xFFFFFFFFu - (unsigned)i);
        }
    }
}

// ---------------- K4: bitonic sort each bin segment (descending) ----------------
__global__ void k_segsort() {
    int b = blockIdx.y;
    int bin = g_thresh[b] + blockIdx.x;
    if (bin >= NBINS) return;
    unsigned cnt = g_hist[b][bin];
    if (cnt <= 1) return;
    unsigned base = g_cursor[b][bin] - cnt;
    __shared__ u64 key[SEGCAP];
    unsigned cc = cnt < (unsigned)SEGCAP ? cnt : (unsigned)SEGCAP;
    unsigned m = 2; while (m < cc) m <<= 1;
    for (unsigned x = threadIdx.x; x < m; x += blockDim.x)
        key[x] = (x < cc) ? g_cand[b][base + x] : 0ull;
    __syncthreads();
    for (unsigned k = 2; k <= m; k <<= 1) {
        for (unsigned j = k >> 1; j > 0; j >>= 1) {
            for (unsigned x = threadIdx.x; x < m; x += blockDim.x) {
                unsigned l = x ^ j;
                if (l > x) {
                    u64 a = key[x], c = key[l];
                    bool up = ((x & k) == 0);
                    if (up ? (a < c) : (a > c)) { key[x] = c; key[l] = a; }
                }
            }
            __syncthreads();
        }
    }
    for (unsigned x = threadIdx.x; x < cc; x += blockDim.x)
        g_cand[b][base + x] = key[x];
}

// ---------------- K5: decode, clip, normalize top-P boxes ----------------
__global__ void k_decode(const float* __restrict__ rpn_bbox,
                         const float* __restrict__ anchors) {
    int p = blockIdx.x * blockDim.x + threadIdx.x;
    int b = blockIdx.y;
    if (p >= PP) return;
    u64 key = g_cand[b][p];
    unsigned idx = 0xFFFFFFFFu - (unsigned)(key & 0xFFFFFFFFull);
    float4 a = *(const float4*)(anchors + (size_t)idx * 4);
    float4 d = *(const float4*)(rpn_bbox + ((size_t)b * NN + idx) * 4);
    d.x *= 0.1f; d.y *= 0.1f; d.z *= 0.2f; d.w *= 0.2f;
    float h = a.z - a.x, w = a.w - a.y;
    float cy = a.x + 0.5f * h, cx = a.y + 0.5f * w;
    cy = cy + d.x * h;
    cx = cx + d.y * w;
    h = h * expf(d.z);
    w = w * expf(d.w);
    float y1 = cy - 0.5f * h, x1 = cx - 0.5f * w;
    float y2 = cy + 0.5f * h, x2 = cx + 0.5f * w;
    y1 = fminf(fmaxf(y1, 0.f), 1024.f);
    x1 = fminf(fmaxf(x1, 0.f), 1024.f);
    y2 = fminf(fmaxf(y2, 0.f), 1024.f);
    x2 = fminf(fmaxf(x2, 0.f), 1024.f);
    const float inv = 1.0f / 1024.0f;
    float4 o = make_float4(y1 * inv, x1 * inv, y2 * inv, x2 * inv);
    g_boxes[b][p] = o;
    g_area[b][p] = (o.z - o.x) * (o.w - o.y);
}

// ---------------- K6: suppression bitmask (upper triangle), 4 i-blocks/CTA ----------------
__global__ void k_mask() {
    int jb = blockIdx.x, b = blockIdx.z;
    int ib0 = blockIdx.y * 4;
    if (jb < ib0) return;                    // whole CTA in lower triangle
    int tid = threadIdx.x;
    int ib = ib0 + (tid >> 6);
    int i = ib * 64 + (tid & 63);
    __shared__ float4 bj[64];
    __shared__ float  aj[64];
    int j0 = jb * 64;
    if (tid < 64) {
        int jt = j0 + tid;
        if (jt < PP) { bj[tid] = g_boxes[b][jt]; aj[tid] = g_area[b][jt]; }
    }
    __syncthreads();
    if (jb < ib || i >= PP) return;          // this thread's row is lower triangle / OOB
    float4 bi = g_boxes[b][i];
    float  ai = g_area[b][i];
    u64 mask = 0ull;
    int jmax = min(64, PP - j0);
    #pragma unroll 4
    for (int jj = 0; jj < jmax; jj++) {
        int j = j0 + jj;
        if (j <= i) continue;
        float4 bx = bj[jj];
        float iy1 = fmaxf(bi.x, bx.x), ix1 = fmaxf(bi.y, bx.y);
        float iy2 = fminf(bi.z, bx.z), ix2 = fminf(bi.w, bx.w);
        float ih = fmaxf(iy2 - iy1, 0.f), iw = fmaxf(ix2 - ix1, 0.f);
        float inter = ih * iw;
        float uni = ai + aj[jj] - inter;
        if (inter > 0.7f * fmaxf(uni, 1e-8f)) mask |= (1ull << jj);
    }
    g_supp[b][i][jb] = mask;
    if (jb == ib) g_diag[b][i] = mask;       // compact diag for k_nms
}

// ---------------- K7: blocked greedy NMS, coalesced suppression update ----------------
__global__ void k_nms(float* __restrict__ out) {
    int b = blockIdx.x, tid = threadIdx.x;
    __shared__ u64 s_diag[64];
    __shared__ u64 s_pre, s_kept;
    __shared__ unsigned s_nz[2];
    __shared__ int s_base, s_prev, s_stop;

    float4* ob = (float4*)(out + (size_t)b * NP * 4);
    for (int x = tid; x < NP; x += blockDim.x) ob[x] = make_float4(0.f, 0.f, 0.f, 0.f);

    u64 acc = 0ull;                          // removed-word `tid` (tid < NW)
    if (tid == 0) { s_base = 0; s_stop = 0; }
    __syncthreads();

    for (int blk = 0; blk < NW; blk++) {
        // coalesced diag fetch + nonzero ballot
        if (tid < 64) {
            int row = min(blk * 64 + tid, PP - 1);
            u64 d = g_diag[b][row];
            s_diag[tid] = d;
            unsigned bal = __ballot_sync(0xffffffffu, d != 0ull);
            if ((tid & 31) == 0) s_nz[tid >> 5] = bal;
        }
        if (tid == blk) s_pre = acc;
        __syncthreads();

        if (tid == 0) {
            u64 jm = (u64)s_nz[0] | ((u64)s_nz[1] << 32);
            u64 alive = ~s_pre;
            if (blk == NW - 1) alive &= (1ull << (PP - (NW - 1) * 64)) - 1ull;
            while (jm) {                      // only rows with nonzero diag (sparse)
                int j = __ffsll((long long)jm) - 1; jm &= jm - 1;
                if ((alive >> j) & 1ull) alive &= ~s_diag[j];
            }
            int cnt = __popcll(alive);
            int rem = NP - s_base;
            while (cnt > rem) {               // truncate highest-index kept bits
                alive &= ~(1ull << (63 - __clzll((long long)alive)));
                cnt--;
            }
            s_kept = alive;
            s_prev = s_base;
            s_base += cnt;
            if (s_base >= NP) s_stop = 1;
        }
        __syncthreads();

        u64 km = s_kept;
        if (tid < 64 && ((km >> tid) & 1ull)) {
            u64 lowmask = (tid == 0) ? 0ull : (km & ((1ull << tid) - 1ull));
            ob[s_prev + __popcll(lowmask)] = g_boxes[b][blk * 64 + tid];
        }
        // coalesced, fixed-trip, predicated OR over the 64 rows of this block
        if (tid < NW && tid > blk) {
            const u64* rp = &g_supp[b][blk * 64][tid];
            #pragma unroll 8
            for (int jj = 0; jj < 64; jj++) {
                int off = (blk * 64 + jj < PP) ? jj * NWPAD : 0;
                u64 v = rp[off];
                acc |= ((km >> jj) & 1ull) ? v : 0ull;
            }
        }
        if (s_stop) break;                    // s_stop read-after-sync (written pre-sync)
        __syncthreads();
    }
}

// ---------------- launch ----------------
extern "C" void kernel_launch(void* const* d_in, const int* in_sizes, int n_in,
                              void* d_out, int out_size) {
    const float* rpn_class = (const float*)d_in[0];
    const float* rpn_bbox  = (const float*)d_in[1];
    const float* anchors   = (const float*)d_in[2];
    float* out = (float*)d_out;

    k_zero<<<(BB * NBINS + 1023) / 1024, 1024>>>();
    dim3 ghist((NN + 255) / 256, BB);
    k_hist<<<ghist, 256>>>(rpn_class);
    k_scan<<<BB, 1024>>>();
    k_scatter<<<ghist, 256>>>(rpn_class);
    k_segsort<<<dim3(NSEG, BB), 256>>>();
    k_decode<<<dim3((PP + 127) / 128, BB), 128>>>(rpn_bbox, anchors);
    k_mask<<<dim3(NW, (NW + 3) / 4, BB), 256>>>();
    k_nms<<<BB, 128>>>(out);
}

// round 4
// speedup vs baseline: 2.1559x; 1.0615x over previous
#include <cuda_runtime.h>
#include <cuda_bf16.h>

#define BB 4
#define NN 261888
#define PP 6000
#define NP 2000
#define NBINS 65536
#define CAP 16384
#define NW 94          // ceil(PP/64)
#define NWPAD 96       // padded gmem row (16B aligned)
#define NWS 97         // smem row stride (odd: conflict-free columns)
#define NSEG 64
#define SEGCAP 4096

typedef unsigned long long u64;

// ---------------- scratch (device globals; no allocations) ----------------
__device__ unsigned int        g_hist[BB][NBINS];
__device__ unsigned int        g_cursor[BB][NBINS];
__device__ int                 g_thresh[BB];
__device__ u64                 g_cand[BB][CAP];
__device__ __align__(16) float4 g_boxes[BB][PP];
__device__ float               g_area[BB][PP];
__device__ __align__(16) u64   g_supp[BB][PP][NWPAD];

// ---------------- K1: histogram over top-16 bits of score ----------------
__global__ void k_hist(const float* __restrict__ rpn_class) {
    int i = blockIdx.x * blockDim.x + threadIdx.x;   // handles elements 2i, 2i+1
    int b = blockIdx.y;
    if (2 * i >= NN) return;
    float4 v = *(const float4*)(rpn_class + (size_t)b * NN * 2 + (size_t)i * 4);
    atomicAdd(&g_hist[b][__float_as_uint(v.y) >> 16], 1u);
    atomicAdd(&g_hist[b][__float_as_uint(v.w) >> 16], 1u);
}

// ---------------- K2: descending prefix sum; cursor bases; threshold ----------------
__global__ void k_scan() {
    int b = blockIdx.x, t = threadIdx.x;
    __shared__ unsigned gs[1024];
    unsigned s = 0;
    #pragma unroll 8
    for (int k = 0; k < 64; k++) s += g_hist[b][t * 64 + k];
    gs[t] = s;
    __syncthreads();
    unsigned self = s;
    for (int off = 1; off < 1024; off <<= 1) {
        unsigned v = (t + off < 1024) ? gs[t + off] : 0u;
        __syncthreads();
        gs[t] += v;
        __syncthreads();
    }
    unsigned run = gs[t] - self;     // count in bins strictly above this 64-group
    int minbin = NBINS;
    for (int k = 63; k >= 0; k--) {
        int bin = t * 64 + k;
        g_cursor[b][bin] = run;
        if (run < PP) minbin = bin;
        run += g_hist[b][bin];
    }
    if (minbin < NBINS) atomicMin(&g_thresh[b], minbin);
}

// ---------------- K3: scatter candidates grouped by bin ----------------
__global__ void k_scatter(const float* __restrict__ rpn_class) {
    int i = blockIdx.x * blockDim.x + threadIdx.x;   // elements 2i, 2i+1
    int b = blockIdx.y;
    if (2 * i >= NN) return;
    float4 v = *(const float4*)(rpn_class + (size_t)b * NN * 2 + (size_t)i * 4);
    int th = g_thresh[b];
    unsigned bits0 = __float_as_uint(v.y);
    unsigned bits1 = __float_as_uint(v.w);
    if ((int)(bits0 >> 16) >= th) {
        unsigned pos = atomicAdd(&g_cursor[b][bits0 >> 16], 1u);
        if (pos < CAP)
            g_cand[b][pos] = ((u64)bits0 << 32) | (u64)(0xFFFFFFFFu - (unsigned)(2 * i));
    }
    if ((int)(bits1 >> 16) >= th) {
        unsigned pos = atomicAdd(&g_cursor[b][bits1 >> 16], 1u);
        if (pos < CAP)
            g_cand[b][pos] = ((u64)bits1 << 32) | (u64)(0xFFFFFFFFu - (unsigned)(2 * i + 1));
    }
}

// ---------------- K4: per-bin bitonic sort + fused decode ----------------
__global__ void k_segsort(const float* __restrict__ rpn_bbox,
                          const float* __restrict__ anchors) {
    int b = blockIdx.y;
    int bin = g_thresh[b] + blockIdx.x;
    if (bin >= NBINS) return;
    unsigned cnt = g_hist[b][bin];
    if (cnt == 0) return;
    unsigned base = g_cursor[b][bin] - cnt;   // cursor is now base+cnt
    __shared__ u64 key[SEGCAP];
    unsigned cc = cnt < (unsigned)SEGCAP ? cnt : (unsigned)SEGCAP;
    unsigned m = 2; while (m < cc) m <<= 1;
    for (unsigned x = threadIdx.x; x < m; x += blockDim.x)
        key[x] = (x < cc) ? g_cand[b][base + x] : 0ull;   // 0 sorts last (keys > 0)
    __syncthreads();
    if (cc > 1) {
        for (unsigned k = 2; k <= m; k <<= 1) {
            for (unsigned j = k >> 1; j > 0; j >>= 1) {
                for (unsigned x = threadIdx.x; x < m; x += blockDim.x) {
                    unsigned l = x ^ j;
                    if (l > x) {
                        u64 a = key[x], c = key[l];
                        bool up = ((x & k) == 0);
                        if (up ? (a < c) : (a > c)) { key[x] = c; key[l] = a; }
                    }
                }
                __syncthreads();
            }
        }
    }
    // fused decode: global rank base+x, keep only < PP
    for (unsigned x = threadIdx.x; x < cc; x += blockDim.x) {
        unsigned p = base + x;
        if (p >= PP) continue;
        unsigned idx = 0xFFFFFFFFu - (unsigned)(key[x] & 0xFFFFFFFFull);
        float4 a = *(const float4*)(anchors + (size_t)idx * 4);
        float4 d = *(const float4*)(rpn_bbox + ((size_t)b * NN + idx) * 4);
        d.x *= 0.1f; d.y *= 0.1f; d.z *= 0.2f; d.w *= 0.2f;
        float h = a.z - a.x, w = a.w - a.y;
        float cy = a.x + 0.5f * h, cx = a.y + 0.5f * w;
        cy = cy + d.x * h;
        cx = cx + d.y * w;
        h = h * expf(d.z);
        w = w * expf(d.w);
        float y1 = cy - 0.5f * h, x1 = cx - 0.5f * w;
        float y2 = cy + 0.5f * h, x2 = cx + 0.5f * w;
        y1 = fminf(fmaxf(y1, 0.f), 1024.f);
        x1 = fminf(fmaxf(x1, 0.f), 1024.f);
        y2 = fminf(fmaxf(y2, 0.f), 1024.f);
        x2 = fminf(fmaxf(x2, 0.f), 1024.f);
        const float inv = 1.0f / 1024.0f;
        float4 o = make_float4(y1 * inv, x1 * inv, y2 * inv, x2 * inv);
        g_boxes[b][p] = o;
        g_area[b][p] = (o.z - o.x) * (o.w - o.y);
    }
}

// ---------------- K6: suppression bitmask (upper triangle), 4 i-blocks/CTA ----------------
__global__ void k_mask() {
    int jb = blockIdx.x, b = blockIdx.z;
    int ib0 = blockIdx.y * 4;
    if (jb < ib0) return;
    int tid = threadIdx.x;
    int ib = ib0 + (tid >> 6);
    int i = ib * 64 + (tid & 63);
    __shared__ float4 bj[64];
    __shared__ float  aj[64];
    int j0 = jb * 64;
    if (tid < 64) {
        int jt = j0 + tid;
        if (jt < PP) { bj[tid] = g_boxes[b][jt]; aj[tid] = g_area[b][jt]; }
    }
    __syncthreads();
    if (jb < ib || i >= PP) return;
    float4 bi = g_boxes[b][i];
    float  ai = g_area[b][i];
    u64 mask = 0ull;
    int jmax = min(64, PP - j0);
    #pragma unroll 4
    for (int jj = 0; jj < jmax; jj++) {
        int j = j0 + jj;
        if (j <= i) continue;
        float4 bx = bj[jj];
        float iy1 = fmaxf(bi.x, bx.x), ix1 = fmaxf(bi.y, bx.y);
        float iy2 = fminf(bi.z, bx.z), ix2 = fminf(bi.w, bx.w);
        float ih = fmaxf(iy2 - iy1, 0.f), iw = fmaxf(ix2 - ix1, 0.f);
        float inter = ih * iw;
        float uni = ai + aj[jj] - inter;
        if (inter > 0.7f * fmaxf(uni, 1e-8f)) mask |= (1ull << jj);
    }
    g_supp[b][i][jb] = mask;
}

// ---------------- K7: blocked greedy NMS, double-buffered smem staging ----------------
__device__ __forceinline__ void cpasync8(unsigned saddr, const void* gaddr) {
    asm volatile("cp.async.ca.shared.global [%0], [%1], 8;\n"
                 :: "r"(saddr), "l"(gaddr) : "memory");
}

__global__ void k_nms(float* __restrict__ out) {
    int b = blockIdx.x, tid = threadIdx.x;
    extern __shared__ u64 sb[];               // 2 buffers of 64*NWS u64
    __shared__ u64 s_pre, s_kept;
    __shared__ unsigned s_nz[2];
    __shared__ int s_base, s_prev, s_stop;

    float4* ob = (float4*)(out + (size_t)b * NP * 4);
    for (int x = tid; x < NP; x += blockDim.x) ob[x] = make_float4(0.f, 0.f, 0.f, 0.f);

    u64 acc = 0ull;                           // removed-word `tid` (tid < NW)
    if (tid == 0) { s_base = 0; s_stop = 0; }

    // stage a block slab: rows blk2*64..+63, words startw..NW-1 (8B cp.async)
    auto issue = [&](int blk2, u64* dst, int startw) {
        for (int r = 0; r < 64; r++) {
            int row = blk2 * 64 + r; if (row >= PP) row = PP - 1;
            const u64* src = &g_supp[b][row][0];
            unsigned sdst = (unsigned)__cvta_generic_to_shared(dst + r * NWS);
            for (int w = startw + tid; w < NW; w += 128)
                cpasync8(sdst + w * 8, src + w);
        }
    };

    issue(0, sb, 0);
    asm volatile("cp.async.commit_group;\n" ::: "memory");
    issue(1, sb + 64 * NWS, 1);
    asm volatile("cp.async.commit_group;\n" ::: "memory");
    __syncthreads();

    for (int blk = 0; blk < NW; blk++) {
        u64* buf = sb + (blk & 1) * 64 * NWS;
        asm volatile("cp.async.wait_group 1;\n" ::: "memory");
        __syncthreads();

        if (tid < 64) {
            u64 d = buf[tid * NWS + blk];     // diag column from staged slab
            unsigned bal = __ballot_sync(0xffffffffu, d != 0ull);
            if ((tid & 31) == 0) s_nz[tid >> 5] = bal;
        }
        if (tid == blk) s_pre = acc;
        __syncthreads();

        if (tid == 0) {
            u64 jm = (u64)s_nz[0] | ((u64)s_nz[1] << 32);
            u64 alive = ~s_pre;
            if (blk == NW - 1) alive &= (1ull << (PP - (NW - 1) * 64)) - 1ull;
            while (jm) {                      // only nonzero-diag rows (sparse)
                int j = __ffsll((long long)jm) - 1; jm &= jm - 1;
                if ((alive >> j) & 1ull) alive &= ~buf[j * NWS + blk];
            }
            int cnt = __popcll(alive);
            int rem = NP - s_base;
            while (cnt > rem) {               // truncate highest-index kept bits
                alive &= ~(1ull << (63 - __clzll((long long)alive)));
                cnt--;
            }
            s_kept = alive;
            s_prev = s_base;
            s_base += cnt;
            if (s_base >= NP) s_stop = 1;
        }
        __syncthreads();

        u64 km = s_kept;
        if (tid < 64 && ((km >> tid) & 1ull)) {
            u64 lowmask = (tid == 0) ? 0ull : (km & ((1ull << tid) - 1ull));
            ob[s_prev + __popcll(lowmask)] = g_boxes[b][blk * 64 + tid];
        }
        if (tid < NW && tid > blk) {          // all-LDS OR, conflict-free stride
            #pragma unroll 8
            for (int jj = 0; jj < 64; jj++) {
                u64 v = buf[jj * NWS + tid];
                acc |= ((km >> jj) & 1ull) ? v : 0ull;
            }
        }
        int stop = s_stop;
        __syncthreads();                      // protect buf before overwrite
        if (stop) break;
        if (blk + 2 < NW) issue(blk + 2, buf, blk + 2);
        asm volatile("cp.async.commit_group;\n" ::: "memory");  // always (keeps wait invariant)
    }
    asm volatile("cp.async.wait_group 0;\n" ::: "memory");
}

// ---------------- launch ----------------
extern "C" void kernel_launch(void* const* d_in, const int* in_sizes, int n_in,
                              void* d_out, int out_size) {
    const float* rpn_class = (const float*)d_in[0];
    const float* rpn_bbox  = (const float*)d_in[1];
    const float* anchors   = (const float*)d_in[2];
    float* out = (float*)d_out;

    void* hist_ptr = nullptr;  cudaGetSymbolAddress(&hist_ptr, g_hist);
    void* th_ptr   = nullptr;  cudaGetSymbolAddress(&th_ptr, g_thresh);
    cudaMemsetAsync(hist_ptr, 0x00, sizeof(unsigned) * BB * NBINS);
    cudaMemsetAsync(th_ptr,   0x7F, sizeof(int) * BB);   // 0x7F7F7F7F > NBINS

    dim3 gpair((NN / 2 + 255) / 256, BB);
    k_hist<<<gpair, 256>>>(rpn_class);
    k_scan<<<BB, 1024>>>();
    k_scatter<<<gpair, 256>>>(rpn_class);
    k_segsort<<<dim3(NSEG, BB), 256>>>(rpn_bbox, anchors);
    k_mask<<<dim3(NW, (NW + 3) / 4, BB), 256>>>();

    int smem = 2 * 64 * NWS * (int)sizeof(u64);          // 99328 B
    cudaFuncSetAttribute(k_nms, cudaFuncAttributeMaxDynamicSharedMemorySize, smem);
    k_nms<<<BB, 128, smem>>>(out);
}

// round 5
// speedup vs baseline: 2.2598x; 1.0482x over previous
#include <cuda_runtime.h>
#include <cuda_bf16.h>

#define BB 4
#define NN 261888
#define PP 6000
#define NP 2000
#define NBINS 65536
#define CAP 16384
#define NW 94          // ceil(PP/64)
#define NWPAD 96       // padded gmem row (16B aligned)
#define NWS 97         // smem row stride (odd: conflict-free columns)
#define NSEG 64
#define SEGCAP 4096

typedef unsigned long long u64;

// ---------------- scratch (device globals; no allocations) ----------------
__device__ unsigned int        g_hist[BB][NBINS];
__device__ unsigned int        g_cursor[BB][NBINS];
__device__ int                 g_thresh[BB];
__device__ u64                 g_cand[BB][CAP];
__device__ __align__(16) float4 g_boxes[BB][PP];
__device__ float               g_area[BB][PP];
__device__ __align__(16) u64   g_supp[BB][PP][NWPAD];

// ---------------- K1: histogram over top-16 bits of score ----------------
__global__ void k_hist(const float* __restrict__ rpn_class) {
    int i = blockIdx.x * blockDim.x + threadIdx.x;   // handles elements 2i, 2i+1
    int b = blockIdx.y;
    if (2 * i >= NN) return;
    float4 v = *(const float4*)(rpn_class + (size_t)b * NN * 2 + (size_t)i * 4);
    atomicAdd(&g_hist[b][__float_as_uint(v.y) >> 16], 1u);
    atomicAdd(&g_hist[b][__float_as_uint(v.w) >> 16], 1u);
}

// ---------------- K2: descending prefix sum; cursor bases; threshold ----------------
__global__ void k_scan() {
    int b = blockIdx.x, t = threadIdx.x;
    __shared__ unsigned gs[1024];
    unsigned s = 0;
    #pragma unroll 8
    for (int k = 0; k < 64; k++) s += g_hist[b][t * 64 + k];
    gs[t] = s;
    __syncthreads();
    unsigned self = s;
    for (int off = 1; off < 1024; off <<= 1) {
        unsigned v = (t + off < 1024) ? gs[t + off] : 0u;
        __syncthreads();
        gs[t] += v;
        __syncthreads();
    }
    unsigned run = gs[t] - self;     // count in bins strictly above this 64-group
    int minbin = NBINS;
    for (int k = 63; k >= 0; k--) {
        int bin = t * 64 + k;
        g_cursor[b][bin] = run;
        if (run < PP) minbin = bin;
        run += g_hist[b][bin];
    }
    if (minbin < NBINS) atomicMin(&g_thresh[b], minbin);
}

// ---------------- K3: scatter candidates grouped by bin ----------------
__global__ void k_scatter(const float* __restrict__ rpn_class) {
    int i = blockIdx.x * blockDim.x + threadIdx.x;   // elements 2i, 2i+1
    int b = blockIdx.y;
    if (2 * i >= NN) return;
    float4 v = *(const float4*)(rpn_class + (size_t)b * NN * 2 + (size_t)i * 4);
    int th = g_thresh[b];
    unsigned bits0 = __float_as_uint(v.y);
    unsigned bits1 = __float_as_uint(v.w);
    if ((int)(bits0 >> 16) >= th) {
        unsigned pos = atomicAdd(&g_cursor[b][bits0 >> 16], 1u);
        if (pos < CAP)
            g_cand[b][pos] = ((u64)bits0 << 32) | (u64)(0xFFFFFFFFu - (unsigned)(2 * i));
    }
    if ((int)(bits1 >> 16) >= th) {
        unsigned pos = atomicAdd(&g_cursor[b][bits1 >> 16], 1u);
        if (pos < CAP)
            g_cand[b][pos] = ((u64)bits1 << 32) | (u64)(0xFFFFFFFFu - (unsigned)(2 * i + 1));
    }
}

// ---------------- K4: per-bin bitonic sort + fused decode ----------------
__global__ void k_segsort(const float* __restrict__ rpn_bbox,
                          const float* __restrict__ anchors) {
    int b = blockIdx.y;
    int bin = g_thresh[b] + blockIdx.x;
    if (bin >= NBINS) return;
    unsigned cnt = g_hist[b][bin];
    if (cnt == 0) return;
    unsigned base = g_cursor[b][bin] - cnt;   // cursor is now base+cnt
    __shared__ u64 key[SEGCAP];
    unsigned cc = cnt < (unsigned)SEGCAP ? cnt : (unsigned)SEGCAP;
    unsigned m = 2; while (m < cc) m <<= 1;
    for (unsigned x = threadIdx.x; x < m; x += blockDim.x)
        key[x] = (x < cc) ? g_cand[b][base + x] : 0ull;   // 0 sorts last (keys > 0)
    __syncthreads();
    if (cc > 1) {
        for (unsigned k = 2; k <= m; k <<= 1) {
            for (unsigned j = k >> 1; j > 0; j >>= 1) {
                for (unsigned x = threadIdx.x; x < m; x += blockDim.x) {
                    unsigned l = x ^ j;
                    if (l > x) {
                        u64 a = key[x], c = key[l];
                        bool up = ((x & k) == 0);
                        if (up ? (a < c) : (a > c)) { key[x] = c; key[l] = a; }
                    }
                }
                __syncthreads();
            }
        }
    }
    // fused decode: global rank base+x, keep only < PP
    for (unsigned x = threadIdx.x; x < cc; x += blockDim.x) {
        unsigned p = base + x;
        if (p >= PP) continue;
        unsigned idx = 0xFFFFFFFFu - (unsigned)(key[x] & 0xFFFFFFFFull);
        float4 a = *(const float4*)(anchors + (size_t)idx * 4);
        float4 d = *(const float4*)(rpn_bbox + ((size_t)b * NN + idx) * 4);
        d.x *= 0.1f; d.y *= 0.1f; d.z *= 0.2f; d.w *= 0.2f;
        float h = a.z - a.x, w = a.w - a.y;
        float cy = a.x + 0.5f * h, cx = a.y + 0.5f * w;
        cy = cy + d.x * h;
        cx = cx + d.y * w;
        h = h * expf(d.z);
        w = w * expf(d.w);
        float y1 = cy - 0.5f * h, x1 = cx - 0.5f * w;
        float y2 = cy + 0.5f * h, x2 = cx + 0.5f * w;
        y1 = fminf(fmaxf(y1, 0.f), 1024.f);
        x1 = fminf(fmaxf(x1, 0.f), 1024.f);
        y2 = fminf(fmaxf(y2, 0.f), 1024.f);
        x2 = fminf(fmaxf(x2, 0.f), 1024.f);
        const float inv = 1.0f / 1024.0f;
        float4 o = make_float4(y1 * inv, x1 * inv, y2 * inv, x2 * inv);
        g_boxes[b][p] = o;
        g_area[b][p] = (o.z - o.x) * (o.w - o.y);
    }
}

// ---------------- K6: suppression bitmask (upper triangle), 4 i-blocks/CTA ----------------
__global__ void k_mask() {
    int jb = blockIdx.x, b = blockIdx.z;
    int ib0 = blockIdx.y * 4;
    if (jb < ib0) return;
    int tid = threadIdx.x;
    int ib = ib0 + (tid >> 6);
    int i = ib * 64 + (tid & 63);
    __shared__ float4 bj[64];
    __shared__ float  aj[64];
    int j0 = jb * 64;
    if (tid < 64) {
        int jt = j0 + tid;
        if (jt < PP) { bj[tid] = g_boxes[b][jt]; aj[tid] = g_area[b][jt]; }
    }
    __syncthreads();
    if (jb < ib || i >= PP) return;
    float4 bi = g_boxes[b][i];
    float  ai = g_area[b][i];
    u64 mask = 0ull;
    int jmax = min(64, PP - j0);
    #pragma unroll 4
    for (int jj = 0; jj < jmax; jj++) {
        int j = j0 + jj;
        if (j <= i) continue;
        float4 bx = bj[jj];
        float iy1 = fmaxf(bi.x, bx.x), ix1 = fmaxf(bi.y, bx.y);
        float iy2 = fminf(bi.z, bx.z), ix2 = fminf(bi.w, bx.w);
        float ih = fmaxf(iy2 - iy1, 0.f), iw = fmaxf(ix2 - ix1, 0.f);
        float inter = ih * iw;
        float uni = ai + aj[jj] - inter;
        if (inter > 0.7f * fmaxf(uni, 1e-8f)) mask |= (1ull << jj);
    }
    g_supp[b][i][jb] = mask;
}

// ---------------- K7: blocked greedy NMS, double-buffered smem staging ----------------
__device__ __forceinline__ void cpasync8(unsigned saddr, const void* gaddr) {
    asm volatile("cp.async.ca.shared.global [%0], [%1], 8;\n"
                 :: "r"(saddr), "l"(gaddr) : "memory");
}

__global__ void k_nms(float* __restrict__ out) {
    int b = blockIdx.x, tid = threadIdx.x;
    extern __shared__ u64 sb[];               // 2 buffers of 64*NWS u64
    __shared__ u64 s_pre, s_kept;
    __shared__ unsigned s_nz[2];
    __shared__ int s_base, s_prev, s_stop;

    float4* ob = (float4*)(out + (size_t)b * NP * 4);
    for (int x = tid; x < NP; x += blockDim.x) ob[x] = make_float4(0.f, 0.f, 0.f, 0.f);

    u64 acc = 0ull;                           // removed-word `tid` (tid < NW)
    if (tid == 0) { s_base = 0; s_stop = 0; }

    // stage a block slab: rows blk2*64..+63, words startw..NW-1 (8B cp.async)
    auto issue = [&](int blk2, u64* dst, int startw) {
        for (int r = 0; r < 64; r++) {
            int row = blk2 * 64 + r; if (row >= PP) row = PP - 1;
            const u64* src = &g_supp[b][row][0];
            unsigned sdst = (unsigned)__cvta_generic_to_shared(dst + r * NWS);
            for (int w = startw + tid; w < NW; w += 128)
                cpasync8(sdst + w * 8, src + w);
        }
    };

    issue(0, sb, 0);
    asm volatile("cp.async.commit_group;\n" ::: "memory");
    issue(1, sb + 64 * NWS, 1);
    asm volatile("cp.async.commit_group;\n" ::: "memory");
    __syncthreads();

    for (int blk = 0; blk < NW; blk++) {
        u64* buf = sb + (blk & 1) * 64 * NWS;
        asm volatile("cp.async.wait_group 1;\n" ::: "memory");
        __syncthreads();

        if (tid < 64) {
            u64 d = buf[tid * NWS + blk];     // diag column from staged slab
            unsigned bal = __ballot_sync(0xffffffffu, d != 0ull);
            if ((tid & 31) == 0) s_nz[tid >> 5] = bal;
        }
        if (tid == blk) s_pre = acc;
        __syncthreads();

        if (tid == 0) {
            u64 jm = (u64)s_nz[0] | ((u64)s_nz[1] << 32);
            u64 alive = ~s_pre;
            if (blk == NW - 1) alive &= (1ull << (PP - (NW - 1) * 64)) - 1ull;
            while (jm) {                      // only nonzero-diag rows (sparse)
                int j = __ffsll((long long)jm) - 1; jm &= jm - 1;
                if ((alive >> j) & 1ull) alive &= ~buf[j * NWS + blk];
            }
            int cnt = __popcll(alive);
            int rem = NP - s_base;
            while (cnt > rem) {               // truncate highest-index kept bits
                alive &= ~(1ull << (63 - __clzll((long long)alive)));
                cnt--;
            }
            s_kept = alive;
            s_prev = s_base;
            s_base += cnt;
            if (s_base >= NP) s_stop = 1;
        }
        __syncthreads();

        u64 km = s_kept;
        if (tid < 64 && ((km >> tid) & 1ull)) {
            u64 lowmask = (tid == 0) ? 0ull : (km & ((1ull << tid) - 1ull));
            ob[s_prev + __popcll(lowmask)] = g_boxes[b][blk * 64 + tid];
        }
        if (tid < NW && tid > blk) {          // all-LDS OR, conflict-free stride
            #pragma unroll 8
            for (int jj = 0; jj < 64; jj++) {
                u64 v = buf[jj * NWS + tid];
                acc |= ((km >> jj) & 1ull) ? v : 0ull;
            }
        }
        int stop = s_stop;
        __syncthreads();                      // protect buf before overwrite
        if (stop) break;
        if (blk + 2 < NW) issue(blk + 2, buf, blk + 2);
        asm volatile("cp.async.commit_group;\n" ::: "memory");  // always (keeps wait invariant)
    }
    asm volatile("cp.async.wait_group 0;\n" ::: "memory");
}

// ---------------- launch ----------------
extern "C" void kernel_launch(void* const* d_in, const int* in_sizes, int n_in,
                              void* d_out, int out_size) {
    const float* rpn_class = (const float*)d_in[0];
    const float* rpn_bbox  = (const float*)d_in[1];
    const float* anchors   = (const float*)d_in[2];
    float* out = (float*)d_out;

    void* hist_ptr = nullptr;  cudaGetSymbolAddress(&hist_ptr, g_hist);
    void* th_ptr   = nullptr;  cudaGetSymbolAddress(&th_ptr, g_thresh);
    cudaMemsetAsync(hist_ptr, 0x00, sizeof(unsigned) * BB * NBINS);
    cudaMemsetAsync(th_ptr,   0x7F, sizeof(int) * BB);   // 0x7F7F7F7F > NBINS

    dim3 gpair((NN / 2 + 255) / 256, BB);
    k_hist<<<gpair, 256>>>(rpn_class);
    k_scan<<<BB, 1024>>>();
    k_scatter<<<gpair, 256>>>(rpn_class);
    k_segsort<<<dim3(NSEG, BB), 256>>>(rpn_bbox, anchors);
    k_mask<<<dim3(NW, (NW + 3) / 4, BB), 256>>>();

    int smem = 2 * 64 * NWS * (int)sizeof(u64);          // 99328 B
    cudaFuncSetAttribute(k_nms, cudaFuncAttributeMaxDynamicSharedMemorySize, smem);
    k_nms<<<BB, 128, smem>>>(out);
}

// round 6
// speedup vs baseline: 2.2996x; 1.0176x over previous
#include <cuda_runtime.h>
#include <cuda_bf16.h>

#define BB 4
#define NN 261888
#define PP 6000
#define NP 2000
#define NBINS 65536
#define CAP 16384
#define NW 94          // ceil(PP/64)
#define NWPAD 96       // padded gmem row (16B aligned)
#define NSEG 64
#define SEGCAP 4096
#define DPAD 6016      // NW*64

typedef unsigned long long u64;

// ---------------- scratch (device globals; no allocations) ----------------
__device__ unsigned int        g_hist[BB][NBINS];
__device__ unsigned int        g_cursor[BB][NBINS];
__device__ int                 g_thresh[BB];
__device__ u64                 g_cand[BB][CAP];
__device__ __align__(16) float4 g_boxes[BB][PP];
__device__ float               g_area[BB][PP];
__device__ __align__(16) u64   g_supp[BB][PP][NWPAD];
__device__ __align__(16) u64   g_diag[BB][PP];
__device__ __align__(16) u64   g_rownz[BB][NW];   // bit r: row blk*64+r has nonzero off-diag

// ---------------- K1: histogram over top-16 bits of score ----------------
__global__ void k_hist(const float* __restrict__ rpn_class) {
    int i = blockIdx.x * blockDim.x + threadIdx.x;   // handles elements 2i, 2i+1
    int b = blockIdx.y;
    if (2 * i >= NN) return;
    float4 v = *(const float4*)(rpn_class + (size_t)b * NN * 2 + (size_t)i * 4);
    atomicAdd(&g_hist[b][__float_as_uint(v.y) >> 16], 1u);
    atomicAdd(&g_hist[b][__float_as_uint(v.w) >> 16], 1u);
}

// ---------------- K2: descending prefix sum; cursor bases; threshold ----------------
__global__ void k_scan() {
    int b = blockIdx.x, t = threadIdx.x;
    __shared__ unsigned gs[1024];
    unsigned s = 0;
    #pragma unroll 8
    for (int k = 0; k < 64; k++) s += g_hist[b][t * 64 + k];
    gs[t] = s;
    __syncthreads();
    unsigned self = s;
    for (int off = 1; off < 1024; off <<= 1) {
        unsigned v = (t + off < 1024) ? gs[t + off] : 0u;
        __syncthreads();
        gs[t] += v;
        __syncthreads();
    }
    unsigned run = gs[t] - self;     // count in bins strictly above this 64-group
    int minbin = NBINS;
    for (int k = 63; k >= 0; k--) {
        int bin = t * 64 + k;
        g_cursor[b][bin] = run;
        if (run < PP) minbin = bin;
        run += g_hist[b][bin];
    }
    if (minbin < NBINS) atomicMin(&g_thresh[b], minbin);
}

// ---------------- K3: scatter candidates grouped by bin ----------------
__global__ void k_scatter(const float* __restrict__ rpn_class) {
    int i = blockIdx.x * blockDim.x + threadIdx.x;   // elements 2i, 2i+1
    int b = blockIdx.y;
    if (2 * i >= NN) return;
    float4 v = *(const float4*)(rpn_class + (size_t)b * NN * 2 + (size_t)i * 4);
    int th = g_thresh[b];
    unsigned bits0 = __float_as_uint(v.y);
    unsigned bits1 = __float_as_uint(v.w);
    if ((int)(bits0 >> 16) >= th) {
        unsigned pos = atomicAdd(&g_cursor[b][bits0 >> 16], 1u);
        if (pos < CAP)
            g_cand[b][pos] = ((u64)bits0 << 32) | (u64)(0xFFFFFFFFu - (unsigned)(2 * i));
    }
    if ((int)(bits1 >> 16) >= th) {
        unsigned pos = atomicAdd(&g_cursor[b][bits1 >> 16], 1u);
        if (pos < CAP)
            g_cand[b][pos] = ((u64)bits1 << 32) | (u64)(0xFFFFFFFFu - (unsigned)(2 * i + 1));
    }
}

// ---------------- K4: per-bin rank-by-counting + fused decode ----------------
__global__ void k_segsort(const float* __restrict__ rpn_bbox,
                          const float* __restrict__ anchors) {
    int b = blockIdx.y;
    int bin = g_thresh[b] + blockIdx.x;
    if (bin >= NBINS) return;
    unsigned cnt = g_hist[b][bin];
    if (cnt == 0) return;
    unsigned base = g_cursor[b][bin] - cnt;   // cursor is now base+cnt
    if (base >= PP) return;                   // whole bin below cut
    __shared__ u64 key[SEGCAP];
    unsigned cc = cnt < (unsigned)SEGCAP ? cnt : (unsigned)SEGCAP;
    for (unsigned x = threadIdx.x; x < cc; x += blockDim.x)
        key[x] = g_cand[b][base + x];
    __syncthreads();
    for (unsigned x = threadIdx.x; x < cc; x += blockDim.x) {
        u64 me = key[x];
        unsigned rank = 0;
        for (unsigned y = 0; y < cc; y++)     // smem broadcast reads
            rank += (key[y] > me);
        unsigned p = base + rank;             // keys unique (idx embedded)
        if (p >= PP) continue;
        unsigned idx = 0xFFFFFFFFu - (unsigned)(me & 0xFFFFFFFFull);
        float4 a = *(const float4*)(anchors + (size_t)idx * 4);
        float4 d = *(const float4*)(rpn_bbox + ((size_t)b * NN + idx) * 4);
        d.x *= 0.1f; d.y *= 0.1f; d.z *= 0.2f; d.w *= 0.2f;
        float h = a.z - a.x, w = a.w - a.y;
        float cy = a.x + 0.5f * h, cx = a.y + 0.5f * w;
        cy = cy + d.x * h;
        cx = cx + d.y * w;
        h = h * expf(d.z);
        w = w * expf(d.w);
        float y1 = cy - 0.5f * h, x1 = cx - 0.5f * w;
        float y2 = cy + 0.5f * h, x2 = cx + 0.5f * w;
        y1 = fminf(fmaxf(y1, 0.f), 1024.f);
        x1 = fminf(fmaxf(x1, 0.f), 1024.f);
        y2 = fminf(fmaxf(y2, 0.f), 1024.f);
        x2 = fminf(fmaxf(x2, 0.f), 1024.f);
        const float inv = 1.0f / 1024.0f;
        float4 o = make_float4(y1 * inv, x1 * inv, y2 * inv, x2 * inv);
        g_boxes[b][p] = o;
        g_area[b][p] = (o.z - o.x) * (o.w - o.y);
    }
}

// ---------------- K6: suppression bitmask (upper tri) + diag + row-nonzero flags ----------------
__global__ void k_mask() {
    int jb = blockIdx.x, b = blockIdx.z;
    int ib0 = blockIdx.y * 4;
    if (jb < ib0) return;
    int tid = threadIdx.x;
    int ib = ib0 + (tid >> 6);
    int i = ib * 64 + (tid & 63);
    __shared__ float4 bj[64];
    __shared__ float  aj[64];
    int j0 = jb * 64;
    if (tid < 64) {
        int jt = j0 + tid;
        if (jt < PP) { bj[tid] = g_boxes[b][jt]; aj[tid] = g_area[b][jt]; }
    }
    __syncthreads();
    if (jb < ib || i >= PP) return;
    float4 bi = g_boxes[b][i];
    float  ai = g_area[b][i];
    u64 mask = 0ull;
    int jmax = min(64, PP - j0);
    #pragma unroll 4
    for (int jj = 0; jj < jmax; jj++) {
        int j = j0 + jj;
        if (j <= i) continue;
        float4 bx = bj[jj];
        float iy1 = fmaxf(bi.x, bx.x), ix1 = fmaxf(bi.y, bx.y);
        float iy2 = fminf(bi.z, bx.z), ix2 = fminf(bi.w, bx.w);
        float ih = fmaxf(iy2 - iy1, 0.f), iw = fmaxf(ix2 - ix1, 0.f);
        float inter = ih * iw;
        float uni = ai + aj[jj] - inter;
        if (inter > 0.7f * fmaxf(uni, 1e-8f)) mask |= (1ull << jj);
    }
    if (jb == ib) {
        g_diag[b][i] = mask;                  // compact diag (g_supp diag word never read)
    } else {
        g_supp[b][i][jb] = mask;
        if (mask) atomicOr(&g_rownz[b][ib], 1ull << (i & 63));
    }
}

// ---------------- K7: blocked greedy NMS, sparsity-driven ----------------
__global__ void __launch_bounds__(128) k_nms(float* __restrict__ out) {
    int b = blockIdx.x, tid = threadIdx.x;
    __shared__ u64 s_diag[DPAD];
    __shared__ u64 s_rownz[NW];
    __shared__ u64 s_pre, s_kept;
    __shared__ unsigned s_nz[2];
    __shared__ int s_base, s_prev, s_stop;

    float4* ob = (float4*)(out + (size_t)b * NP * 4);
    for (int x = tid; x < NP; x += blockDim.x) ob[x] = make_float4(0.f, 0.f, 0.f, 0.f);
    for (int x = tid; x < DPAD; x += blockDim.x)
        s_diag[x] = (x < PP) ? g_diag[b][x] : 0ull;
    for (int x = tid; x < NW; x += blockDim.x) s_rownz[x] = g_rownz[b][x];

    u64 acc = 0ull;                           // removed-word `tid` (tid < NW)
    if (tid == 0) { s_base = 0; s_stop = 0; }
    __syncthreads();

    for (int blk = 0; blk < NW; blk++) {
        if (tid < 64) {
            u64 d = s_diag[blk * 64 + tid];
            unsigned bal = __ballot_sync(0xffffffffu, d != 0ull);
            if ((tid & 31) == 0) s_nz[tid >> 5] = bal;
        }
        if (tid == blk) s_pre = acc;
        __syncthreads();

        if (tid == 0) {
            u64 jm = (u64)s_nz[0] | ((u64)s_nz[1] << 32);
            u64 alive = ~s_pre;
            if (blk == NW - 1) alive &= (1ull << (PP - (NW - 1) * 64)) - 1ull;
            while (jm) {                      // only nonzero-diag rows (sparse)
                int j = __ffsll((long long)jm) - 1; jm &= jm - 1;
                if ((alive >> j) & 1ull) alive &= ~s_diag[blk * 64 + j];
            }
            int cnt = __popcll(alive);
            int rem = NP - s_base;
            while (cnt > rem) {               // truncate highest-index kept bits
                alive &= ~(1ull << (63 - __clzll((long long)alive)));
                cnt--;
            }
            s_kept = alive;
            s_prev = s_base;
            s_base += cnt;
            if (s_base >= NP) s_stop = 1;
        }
        __syncthreads();

        u64 km = s_kept;
        if (tid < 64 && ((km >> tid) & 1ull)) {
            u64 lowmask = (tid == 0) ? 0ull : (km & ((1ull << tid) - 1ull));
            ob[s_prev + __popcll(lowmask)] = g_boxes[b][blk * 64 + tid];
        }
        // cross-block update: only kept rows flagged nonzero (rare), coalesced LDG
        if (tid < NW && tid > blk) {
            u64 nz = s_rownz[blk] & km;
            while (nz) {
                int j = __ffsll((long long)nz) - 1; nz &= nz - 1;
                acc |= g_supp[b][blk * 64 + j][tid];
            }
        }
        if (s_stop) break;
    }
}

// ---------------- launch ----------------
extern "C" void kernel_launch(void* const* d_in, const int* in_sizes, int n_in,
                              void* d_out, int out_size) {
    const float* rpn_class = (const float*)d_in[0];
    const float* rpn_bbox  = (const float*)d_in[1];
    const float* anchors   = (const float*)d_in[2];
    float* out = (float*)d_out;

    void* hist_ptr = nullptr;  cudaGetSymbolAddress(&hist_ptr, g_hist);
    void* th_ptr   = nullptr;  cudaGetSymbolAddress(&th_ptr, g_thresh);
    void* nz_ptr   = nullptr;  cudaGetSymbolAddress(&nz_ptr, g_rownz);
    cudaMemsetAsync(hist_ptr, 0x00, sizeof(unsigned) * BB * NBINS);
    cudaMemsetAsync(th_ptr,   0x7F, sizeof(int) * BB);   // 0x7F7F7F7F > NBINS
    cudaMemsetAsync(nz_ptr,   0x00, sizeof(u64) * BB * NW);

    dim3 gpair((NN / 2 + 255) / 256, BB);
    k_hist<<<gpair, 256>>>(rpn_class);
    k_scan<<<BB, 1024>>>();
    k_scatter<<<gpair, 256>>>(rpn_class);
    k_segsort<<<dim3(NSEG, BB), 1024>>>(rpn_bbox, anchors);
    k_mask<<<dim3(NW, (NW + 3) / 4, BB), 256>>>();
    k_nms<<<BB, 128>>>(out);
}

// round 7
// speedup vs baseline: 2.7957x; 1.2158x over previous
#include <cuda_runtime.h>
#include <cuda_bf16.h>

#define BB 4
#define NN 261888
#define PP 6000
#define NP 2000
#define NBINS 65536
#define CAP 16384
#define NW 94          // ceil(PP/64)
#define NWPAD 96       // padded gmem row (16B aligned)
#define SEGCAP 4096
#define DPAD 6016      // NW*64
#define NCTA 148
#define RANKP 4        // CTAs per bin in rank phase
#define NPAIR (BB * 64)

typedef unsigned long long u64;

// ---------------- scratch (device globals; no allocations) ----------------
__device__ unsigned int        g_hist[BB][NBINS];
__device__ unsigned int        g_cursor[BB][NBINS];
__device__ int                 g_thresh[BB];
__device__ unsigned int        g_bar[2];
__device__ u64                 g_cand[BB][CAP];
__device__ __align__(16) float4 g_boxes[BB][PP];
__device__ float               g_area[BB][PP];
__device__ __align__(16) u64   g_supp[BB][PP][NWPAD];
__device__ __align__(16) u64   g_diag[BB][PP];
__device__ __align__(16) u64   g_rownz[BB][NW];

// bin -> physical slot: rotate so consecutive bins are 8KB apart (atomic spread),
// while scan's fixed-k warp accesses stay coalesced (stride-2 words).
__device__ __forceinline__ int hslot(int bin) {
    return ((bin & 31) << 11) | (bin >> 5);
}

// ---------------- K1: histogram (rotated bins) + init of small state ----------------
__global__ void k_hist(const float* __restrict__ rpn_class) {
    int i = blockIdx.x * blockDim.x + threadIdx.x;   // elements 2i, 2i+1
    int b = blockIdx.y;
    if (blockIdx.x == 0) {                            // fold tiny inits here
        if (threadIdx.x == 0) g_thresh[b] = NBINS;
        if (threadIdx.x < NW) g_rownz[b][threadIdx.x] = 0ull;
        if (b == 0 && threadIdx.x < 2) g_bar[threadIdx.x] = 0u;
    }
    if (2 * i >= NN) return;
    float4 v = *(const float4*)(rpn_class + (size_t)b * NN * 2 + (size_t)i * 4);
    atomicAdd(&g_hist[b][hslot(__float_as_uint(v.y) >> 16)], 1u);
    atomicAdd(&g_hist[b][hslot(__float_as_uint(v.w) >> 16)], 1u);
}

// ---------------- K2: descending prefix sum; cursor bases; threshold ----------------
__global__ void k_scan() {
    int b = blockIdx.x, t = threadIdx.x;
    __shared__ unsigned gs[1024];
    unsigned s = 0;
    #pragma unroll 8
    for (int k = 0; k < 64; k++) s += g_hist[b][hslot(t * 64 + k)];
    gs[t] = s;
    __syncthreads();
    unsigned self = s;
    for (int off = 1; off < 1024; off <<= 1) {
        unsigned v = (t + off < 1024) ? gs[t + off] : 0u;
        __syncthreads();
        gs[t] += v;
        __syncthreads();
    }
    unsigned run = gs[t] - self;
    int minbin = NBINS;
    for (int k = 63; k >= 0; k--) {
        int bin = t * 64 + k;
        int hs = hslot(bin);
        g_cursor[b][hs] = run;
        if (run < PP) minbin = bin;
        run += g_hist[b][hs];
    }
    if (minbin < NBINS) atomicMin(&g_thresh[b], minbin);
}

// ---------------- K3: scatter candidates grouped by bin ----------------
__global__ void k_scatter(const float* __restrict__ rpn_class) {
    int i = blockIdx.x * blockDim.x + threadIdx.x;
    int b = blockIdx.y;
    if (2 * i >= NN) return;
    float4 v = *(const float4*)(rpn_class + (size_t)b * NN * 2 + (size_t)i * 4);
    int th = g_thresh[b];
    unsigned bits0 = __float_as_uint(v.y);
    unsigned bits1 = __float_as_uint(v.w);
    if ((int)(bits0 >> 16) >= th) {
        unsigned pos = atomicAdd(&g_cursor[b][hslot(bits0 >> 16)], 1u);
        if (pos < CAP)
            g_cand[b][pos] = ((u64)bits0 << 32) | (u64)(0xFFFFFFFFu - (unsigned)(2 * i));
    }
    if ((int)(bits1 >> 16) >= th) {
        unsigned pos = atomicAdd(&g_cursor[b][hslot(bits1 >> 16)], 1u);
        if (pos < CAP)
            g_cand[b][pos] = ((u64)bits1 << 32) | (u64)(0xFFFFFFFFu - (unsigned)(2 * i + 1));
    }
}

// ---------------- software grid barrier (148 co-resident CTAs) ----------------
__device__ __forceinline__ void bar_arrive(int idx) {
    __syncthreads();
    if (threadIdx.x == 0) {
        __threadfence();
        atomicAdd(&g_bar[idx], 1u);
    }
}
__device__ __forceinline__ void bar_wait(int idx) {
    if (threadIdx.x == 0) {
        volatile unsigned* p = &g_bar[idx];
        while (*p < NCTA) __nanosleep(64);
        __threadfence();
    }
    __syncthreads();
}

// ---------------- K4 (fused): rank+decode -> mask -> nms ----------------
__global__ void __launch_bounds__(256) k_fused(const float* __restrict__ rpn_bbox,
                                               const float* __restrict__ anchors,
                                               float* __restrict__ out) {
    extern __shared__ u64 sh[];
    int cta = blockIdx.x, tid = threadIdx.x;

    // ======== phase 1: per-bin rank-by-count + fused decode ========
    for (int slot = cta; slot < NPAIR * RANKP; slot += NCTA) {
        int pair = slot / RANKP, part = slot % RANKP;
        int b = pair >> 6, binoff = pair & 63;
        int bin = g_thresh[b] + binoff;
        if (bin >= NBINS) continue;
        int hs = hslot(bin);
        unsigned cnt = g_hist[b][hs];
        if (cnt == 0) continue;
        unsigned base = g_cursor[b][hs] - cnt;
        if (base >= PP) continue;
        unsigned cc = cnt < (unsigned)SEGCAP ? cnt : (unsigned)SEGCAP;
        u64* key = sh;
        for (unsigned x = tid; x < cc; x += 256) key[x] = g_cand[b][base + x];
        __syncthreads();
        unsigned lo = (unsigned)(((u64)cc * part) / RANKP);
        unsigned hi = (unsigned)(((u64)cc * (part + 1)) / RANKP);
        for (unsigned x = lo + tid; x < hi; x += 256) {
            u64 me = key[x];
            unsigned rank = 0;
            for (unsigned y = 0; y < cc; y++) rank += (key[y] > me);
            unsigned p = base + rank;                 // keys unique (idx embedded)
            if (p >= PP) continue;
            unsigned idx = 0xFFFFFFFFu - (unsigned)(me & 0xFFFFFFFFull);
            float4 a = *(const float4*)(anchors + (size_t)idx * 4);
            float4 d = *(const float4*)(rpn_bbox + ((size_t)b * NN + idx) * 4);
            d.x *= 0.1f; d.y *= 0.1f; d.z *= 0.2f; d.w *= 0.2f;
            float h = a.z - a.x, w = a.w - a.y;
            float cy = a.x + 0.5f * h, cx = a.y + 0.5f * w;
            cy = cy + d.x * h;
            cx = cx + d.y * w;
            h = h * expf(d.z);
            w = w * expf(d.w);
            float y1 = cy - 0.5f * h, x1 = cx - 0.5f * w;
            float y2 = cy + 0.5f * h, x2 = cx + 0.5f * w;
            y1 = fminf(fmaxf(y1, 0.f), 1024.f);
            x1 = fminf(fmaxf(x1, 0.f), 1024.f);
            y2 = fminf(fmaxf(y2, 0.f), 1024.f);
            x2 = fminf(fmaxf(x2, 0.f), 1024.f);
            const float inv = 1.0f / 1024.0f;
            float4 o = make_float4(y1 * inv, x1 * inv, y2 * inv, x2 * inv);
            g_boxes[b][p] = o;
            g_area[b][p] = (o.z - o.x) * (o.w - o.y);
        }
        __syncthreads();
    }
    bar_arrive(0);
    bar_wait(0);

    // ======== phase 2: suppression bitmask tiles (upper triangle) ========
    {
        float4* bj = (float4*)sh;
        float*  aj = (float*)(bj + 64);
        const int NIBG = (NW + 3) / 4;                // 24
        const int PER_B = NW * NIBG;                  // 2256
        for (int st = cta; st < BB * PER_B; st += NCTA) {
            int b = st / PER_B;
            int r = st % PER_B;
            int jb = r / NIBG, ibg = r % NIBG;
            if (jb < ibg * 4) continue;               // lower triangle supertile
            int ib = ibg * 4 + (tid >> 6);
            int i = ib * 64 + (tid & 63);
            int j0 = jb * 64;
            if (tid < 64) {
                int jt = j0 + tid;
                if (jt < PP) { bj[tid] = g_boxes[b][jt]; aj[tid] = g_area[b][jt]; }
            }
            __syncthreads();
            if (jb >= ib && i < PP) {
                float4 bi = g_boxes[b][i];
                float  ai = g_area[b][i];
                u64 mask = 0ull;
                int jmax = min(64, PP - j0);
                #pragma unroll 4
                for (int jj = 0; jj < jmax; jj++) {
                    if (j0 + jj <= i) continue;
                    float4 bx = bj[jj];
                    float iy1 = fmaxf(bi.x, bx.x), ix1 = fmaxf(bi.y, bx.y);
                    float iy2 = fminf(bi.z, bx.z), ix2 = fminf(bi.w, bx.w);
                    float ih = fmaxf(iy2 - iy1, 0.f), iw = fmaxf(ix2 - ix1, 0.f);
                    float inter = ih * iw;
                    float uni = ai + aj[jj] - inter;
                    if (inter > 0.7f * fmaxf(uni, 1e-8f)) mask |= (1ull << jj);
                }
                if (jb == ib) {
                    g_diag[b][i] = mask;
                } else {
                    g_supp[b][i][jb] = mask;
                    if (mask) atomicOr(&g_rownz[b][ib], 1ull << (i & 63));
                }
            }
            __syncthreads();
        }
    }
    bar_arrive(1);
    if (cta >= BB) return;                            // only 4 CTAs run NMS
    bar_wait(1);

    // ======== phase 3: blocked greedy NMS (sparsity-driven) ========
    {
        int b = cta;
        u64* s_diag = sh;
        u64* s_rownz = sh + DPAD;
        __shared__ u64 s_pre, s_kept;
        __shared__ unsigned s_nz[2];
        __shared__ int s_base, s_prev, s_stop;

        float4* ob = (float4*)(out + (size_t)b * NP * 4);
        for (int x = tid; x < NP; x += 256) ob[x] = make_float4(0.f, 0.f, 0.f, 0.f);
        for (int x = tid; x < DPAD; x += 256)
            s_diag[x] = (x < PP) ? g_diag[b][x] : 0ull;
        for (int x = tid; x < NW; x += 256) s_rownz[x] = g_rownz[b][x];

        u64 acc = 0ull;                               // removed-word `tid` (tid < NW)
        if (tid == 0) { s_base = 0; s_stop = 0; }
        __syncthreads();

        for (int blk = 0; blk < NW; blk++) {
            if (tid < 64) {
                u64 d = s_diag[blk * 64 + tid];
                unsigned bal = __ballot_sync(0xffffffffu, d != 0ull);
                if ((tid & 31) == 0) s_nz[tid >> 5] = bal;
            }
            if (tid == blk) s_pre = acc;
            __syncthreads();

            if (tid == 0) {
                u64 jm = (u64)s_nz[0] | ((u64)s_nz[1] << 32);
                u64 alive = ~s_pre;
                if (blk == NW - 1) alive &= (1ull << (PP - (NW - 1) * 64)) - 1ull;
                while (jm) {
                    int j = __ffsll((long long)jm) - 1; jm &= jm - 1;
                    if ((alive >> j) & 1ull) alive &= ~s_diag[blk * 64 + j];
                }
                int cnt = __popcll(alive);
                int rem = NP - s_base;
                while (cnt > rem) {
                    alive &= ~(1ull << (63 - __clzll((long long)alive)));
                    cnt--;
                }
                s_kept = alive;
                s_prev = s_base;
                s_base += cnt;
                if (s_base >= NP) s_stop = 1;
            }
            __syncthreads();

            u64 km = s_kept;
            if (tid < 64 && ((km >> tid) & 1ull)) {
                u64 lowmask = (tid == 0) ? 0ull : (km & ((1ull << tid) - 1ull));
                ob[s_prev + __popcll(lowmask)] = g_boxes[b][blk * 64 + tid];
            }
            if (tid < NW && tid > blk) {
                u64 nz = s_rownz[blk] & km;
                while (nz) {
                    int j = __ffsll((long long)nz) - 1; nz &= nz - 1;
                    acc |= g_supp[b][blk * 64 + j][tid];
                }
            }
            if (s_stop) break;
        }
    }
}

// ---------------- launch ----------------
extern "C" void kernel_launch(void* const* d_in, const int* in_sizes, int n_in,
                              void* d_out, int out_size) {
    const float* rpn_class = (const float*)d_in[0];
    const float* rpn_bbox  = (const float*)d_in[1];
    const float* anchors   = (const float*)d_in[2];
    float* out = (float*)d_out;

    void* hist_ptr = nullptr;  cudaGetSymbolAddress(&hist_ptr, g_hist);
    cudaMemsetAsync(hist_ptr, 0x00, sizeof(unsigned) * BB * NBINS);

    dim3 gpair((NN / 2 + 255) / 256, BB);
    k_hist<<<gpair, 256>>>(rpn_class);
    k_scan<<<BB, 1024>>>();
    k_scatter<<<gpair, 256>>>(rpn_class);

    int smem = (DPAD + NW + 2) * (int)sizeof(u64);    // 48.9KB (covers all phases)
    cudaFuncSetAttribute(k_fused, cudaFuncAttributeMaxDynamicSharedMemorySize, smem);
    k_fused<<<NCTA, 256, smem>>>(rpn_bbox, anchors, out);
}

// round 8
// speedup vs baseline: 3.7464x; 1.3400x over previous
#include <cuda_runtime.h>
#include <cuda_bf16.h>

#define BB 4
#define NN 261888
#define NH (NN / 2)
#define PP 6000
#define NP 2000
#define NBINS 65536
#define CAP 16384
#define NW 94          // ceil(PP/64)
#define NWPAD 96       // padded gmem row (16B aligned)
#define SEGCAP 4096
#define DPAD 6016      // NW*64
#define NCTA 148
#define NTH 1024
#define NS 6
#define HBASE 0x3C00   // smem-privatized bins [HBASE, HBASE+HSPAN): scores >= 2^-7
#define HSPAN 4096

typedef unsigned long long u64;

// ---------------- scratch (device globals; no allocations) ----------------
__device__ unsigned int        g_hist[BB][NBINS];
__device__ unsigned int        g_cursor[BB][NBINS];
__device__ int                 g_thresh[BB];
__device__ unsigned int        g_barrier[NS];     // zero-init; self-resetting
__device__ u64                 g_cand[BB][CAP];
__device__ __align__(16) float4 g_boxes[BB][PP];
__device__ float               g_area[BB][PP];
__device__ __align__(16) u64   g_supp[BB][PP][NWPAD];
__device__ __align__(16) u64   g_diag[BB][PP];
__device__ __align__(16) u64   g_rownz[BB][NW];

// bin -> physical slot: consecutive bins 8KB apart (atomic spread), scan stays coalesced
__device__ __forceinline__ int hslot(int bin) {
    return ((bin & 31) << 11) | (bin >> 5);
}

// grid barrier over NCTA co-resident CTAs; CTA0 resets slot s-1 after passing s
__device__ __forceinline__ void gbar(int s) {
    __syncthreads();
    if (threadIdx.x == 0) {
        __threadfence();
        atomicAdd(&g_barrier[s], 1u);
        while (((volatile unsigned*)g_barrier)[s] < NCTA) __nanosleep(64);
        __threadfence();
        if (blockIdx.x == 0 && s > 0) atomicExch(&g_barrier[s - 1], 0u);
    }
    __syncthreads();
}

__global__ void __launch_bounds__(NTH, 1)
k_all(const float* __restrict__ rpn_class,
      const float* __restrict__ rpn_bbox,
      const float* __restrict__ anchors,
      float* __restrict__ out) {
    extern __shared__ u64 sh[];
    const int cta = blockIdx.x, tid = threadIdx.x;
    const int gtid = cta * NTH + tid;
    const int GT = NCTA * NTH;
    const int bb = cta & 3, cs = cta >> 2;        // batch slice for hist/scatter (37 CTAs/batch)

    // ---- phase 0: zero/init persistent state; reset last barrier slot ----
    if (cta == 0 && tid == 0) atomicExch(&g_barrier[NS - 1], 0u);
    for (int x = gtid; x < BB * NBINS; x += GT) ((unsigned*)g_hist)[x] = 0u;
    for (int x = gtid; x < BB * NW; x += GT) ((u64*)g_rownz)[x] = 0ull;
    if (gtid < BB) g_thresh[gtid] = NBINS;
    gbar(0);

    // ---- phase 1: histogram (smem-privatized hot bins) ----
    {
        unsigned* hh = (unsigned*)sh;             // 4096 hot-bin counters
        for (int x = tid; x < HSPAN; x += NTH) hh[x] = 0u;
        __syncthreads();
        for (int i = cs * NTH + tid; i < NH; i += 37 * NTH) {
            float4 v = *(const float4*)(rpn_class + (size_t)bb * NN * 2 + (size_t)i * 4);
            unsigned b0 = __float_as_uint(v.y) >> 16;
            unsigned b1 = __float_as_uint(v.w) >> 16;
            if (b0 >= HBASE) atomicAdd(&hh[b0 - HBASE], 1u);
            else             atomicAdd(&g_hist[bb][hslot(b0)], 1u);
            if (b1 >= HBASE) atomicAdd(&hh[b1 - HBASE], 1u);
            else             atomicAdd(&g_hist[bb][hslot(b1)], 1u);
        }
        __syncthreads();
        for (int x = tid; x < HSPAN; x += NTH) {
            unsigned c = hh[x];
            if (c) atomicAdd(&g_hist[bb][hslot(HBASE + x)], c);
        }
    }
    gbar(1);

    // ---- phase 2: descending prefix sum, cursor bases, threshold (CTAs 0..3) ----
    if (cta < BB) {
        int b = cta;
        unsigned* gs = (unsigned*)sh;
        unsigned s = 0;
        #pragma unroll 8
        for (int k = 0; k < 64; k++) s += g_hist[b][hslot(tid * 64 + k)];
        gs[tid] = s;
        __syncthreads();
        unsigned self = s;
        for (int off = 1; off < 1024; off <<= 1) {
            unsigned v = (tid + off < 1024) ? gs[tid + off] : 0u;
            __syncthreads();
            gs[tid] += v;
            __syncthreads();
        }
        unsigned run = gs[tid] - self;
        int minbin = NBINS;
        for (int k = 63; k >= 0; k--) {
            int bin = tid * 64 + k;
            int hs = hslot(bin);
            g_cursor[b][hs] = run;
            if (run < PP) minbin = bin;
            run += g_hist[b][hs];
        }
        if (minbin < NBINS) atomicMin(&g_thresh[b], minbin);
    }
    gbar(2);

    // ---- phase 3: scatter candidates grouped by bin ----
    {
        int th = g_thresh[bb];
        for (int i = cs * NTH + tid; i < NH; i += 37 * NTH) {
            float4 v = *(const float4*)(rpn_class + (size_t)bb * NN * 2 + (size_t)i * 4);
            unsigned bits0 = __float_as_uint(v.y);
            unsigned bits1 = __float_as_uint(v.w);
            if ((int)(bits0 >> 16) >= th) {
                unsigned pos = atomicAdd(&g_cursor[bb][hslot(bits0 >> 16)], 1u);
                if (pos < CAP)
                    g_cand[bb][pos] = ((u64)bits0 << 32) | (u64)(0xFFFFFFFFu - (unsigned)(2 * i));
            }
            if ((int)(bits1 >> 16) >= th) {
                unsigned pos = atomicAdd(&g_cursor[bb][hslot(bits1 >> 16)], 1u);
                if (pos < CAP)
                    g_cand[bb][pos] = ((u64)bits1 << 32) | (u64)(0xFFFFFFFFu - (unsigned)(2 * i + 1));
            }
        }
    }
    gbar(3);

    // ---- phase 4: per-bin rank-by-count + fused decode ----
    for (int slot = cta; slot < BB * 64; slot += NCTA) {
        int b = slot >> 6, binoff = slot & 63;
        int bin = g_thresh[b] + binoff;
        if (bin >= NBINS) continue;
        int hs = hslot(bin);
        unsigned cnt = g_hist[b][hs];
        if (cnt == 0) continue;
        unsigned base = g_cursor[b][hs] - cnt;
        if (base >= PP) continue;
        unsigned cc = cnt < (unsigned)SEGCAP ? cnt : (unsigned)SEGCAP;
        u64* key = sh;
        for (unsigned x = tid; x < cc; x += NTH) key[x] = g_cand[b][base + x];
        __syncthreads();
        for (unsigned x = tid; x < cc; x += NTH) {
            u64 me = key[x];
            unsigned rank = 0;
            for (unsigned y = 0; y < cc; y++) rank += (key[y] > me);
            unsigned p = base + rank;                 // keys unique (idx embedded)
            if (p >= PP) continue;
            unsigned idx = 0xFFFFFFFFu - (unsigned)(me & 0xFFFFFFFFull);
            float4 a = *(const float4*)(anchors + (size_t)idx * 4);
            float4 d = *(const float4*)(rpn_bbox + ((size_t)b * NN + idx) * 4);
            d.x *= 0.1f; d.y *= 0.1f; d.z *= 0.2f; d.w *= 0.2f;
            float h = a.z - a.x, w = a.w - a.y;
            float cy = a.x + 0.5f * h, cx = a.y + 0.5f * w;
            cy = cy + d.x * h;
            cx = cx + d.y * w;
            h = h * expf(d.z);
            w = w * expf(d.w);
            float y1 = cy - 0.5f * h, x1 = cx - 0.5f * w;
            float y2 = cy + 0.5f * h, x2 = cx + 0.5f * w;
            y1 = fminf(fmaxf(y1, 0.f), 1024.f);
            x1 = fminf(fmaxf(x1, 0.f), 1024.f);
            y2 = fminf(fmaxf(y2, 0.f), 1024.f);
            x2 = fminf(fmaxf(x2, 0.f), 1024.f);
            const float inv = 1.0f / 1024.0f;
            float4 o = make_float4(y1 * inv, x1 * inv, y2 * inv, x2 * inv);
            g_boxes[b][p] = o;
            g_area[b][p] = (o.z - o.x) * (o.w - o.y);
        }
        __syncthreads();
    }
    gbar(4);

    // ---- phase 5: suppression bitmask tiles (upper triangle), 16 i-blocks/CTA ----
    {
        float4* bj = (float4*)sh;
        float*  aj = (float*)(bj + 64);
        const int NIBG = (NW + 15) / 16;              // 6
        const int PER_B = NW * NIBG;                  // 564
        for (int st = cta; st < BB * PER_B; st += NCTA) {
            int b = st / PER_B;
            int r = st % PER_B;
            int jb = r / NIBG, ibg = r % NIBG;
            if (jb < ibg * 16) continue;              // lower-triangle supertile
            int ib = ibg * 16 + (tid >> 6);
            int i = ib * 64 + (tid & 63);
            int j0 = jb * 64;
            if (tid < 64) {
                int jt = j0 + tid;
                if (jt < PP) { bj[tid] = g_boxes[b][jt]; aj[tid] = g_area[b][jt]; }
            }
            __syncthreads();
            if (jb >= ib && i < PP) {
                float4 bi = g_boxes[b][i];
                float  ai = g_area[b][i];
                u64 mask = 0ull;
                int jmax = min(64, PP - j0);
                #pragma unroll 4
                for (int jj = 0; jj < jmax; jj++) {
                    if (j0 + jj <= i) continue;
                    float4 bx = bj[jj];
                    float iy1 = fmaxf(bi.x, bx.x), ix1 = fmaxf(bi.y, bx.y);
                    float iy2 = fminf(bi.z, bx.z), ix2 = fminf(bi.w, bx.w);
                    float ih = fmaxf(iy2 - iy1, 0.f), iw = fmaxf(ix2 - ix1, 0.f);
                    float inter = ih * iw;
                    float uni = ai + aj[jj] - inter;
                    if (inter > 0.7f * fmaxf(uni, 1e-8f)) mask |= (1ull << jj);
                }
                if (jb == ib) {
                    g_diag[b][i] = mask;
                } else {
                    g_supp[b][i][jb] = mask;
                    if (mask) atomicOr(&g_rownz[b][ib], 1ull << (i & 63));
                }
            }
            __syncthreads();
        }
    }
    gbar(5);
    if (cta >= BB) return;                            // only 4 CTAs run NMS

    // ---- phase 6: blocked greedy NMS (sparsity-driven) ----
    {
        int b = cta;
        u64* s_diag = sh;
        u64* s_rownz = sh + DPAD;
        __shared__ u64 s_pre, s_kept;
        __shared__ unsigned s_nz[2];
        __shared__ int s_base, s_prev, s_stop;

        float4* ob = (float4*)(out + (size_t)b * NP * 4);
        for (int x = tid; x < NP; x += NTH) ob[x] = make_float4(0.f, 0.f, 0.f, 0.f);
        for (int x = tid; x < DPAD; x += NTH)
            s_diag[x] = (x < PP) ? g_diag[b][x] : 0ull;
        for (int x = tid; x < NW; x += NTH) s_rownz[x] = g_rownz[b][x];

        u64 acc = 0ull;                               // removed-word `tid` (tid < NW)
        if (tid == 0) { s_base = 0; s_stop = 0; }
        __syncthreads();

        for (int blk = 0; blk < NW; blk++) {
            if (tid < 64) {
                u64 d = s_diag[blk * 64 + tid];
                unsigned bal = __ballot_sync(0xffffffffu, d != 0ull);
                if ((tid & 31) == 0) s_nz[tid >> 5] = bal;
            }
            if (tid == blk) s_pre = acc;
            __syncthreads();

            if (tid == 0) {
                u64 jm = (u64)s_nz[0] | ((u64)s_nz[1] << 32);
                u64 alive = ~s_pre;
                if (blk == NW - 1) alive &= (1ull << (PP - (NW - 1) * 64)) - 1ull;
                while (jm) {
                    int j = __ffsll((long long)jm) - 1; jm &= jm - 1;
                    if ((alive >> j) & 1ull) alive &= ~s_diag[blk * 64 + j];
                }
                int cnt = __popcll(alive);
                int rem = NP - s_base;
                while (cnt > rem) {
                    alive &= ~(1ull << (63 - __clzll((long long)alive)));
                    cnt--;
                }
                s_kept = alive;
                s_prev = s_base;
                s_base += cnt;
                if (s_base >= NP) s_stop = 1;
            }
            __syncthreads();

            u64 km = s_kept;
            if (tid < 64 && ((km >> tid) & 1ull)) {
                u64 lowmask = (tid == 0) ? 0ull : (km & ((1ull << tid) - 1ull));
                ob[s_prev + __popcll(lowmask)] = g_boxes[b][blk * 64 + tid];
            }
            if (tid < NW && tid > blk) {
                u64 nz = s_rownz[blk] & km;
                while (nz) {
                    int j = __ffsll((long long)nz) - 1; nz &= nz - 1;
                    acc |= g_supp[b][blk * 64 + j][tid];
                }
            }
            if (s_stop) break;
        }
    }
}

// ---------------- launch ----------------
extern "C" void kernel_launch(void* const* d_in, const int* in_sizes, int n_in,
                              void* d_out, int out_size) {
    const float* rpn_class = (const float*)d_in[0];
    const float* rpn_bbox  = (const float*)d_in[1];
    const float* anchors   = (const float*)d_in[2];
    float* out = (float*)d_out;

    int smem = 131072;   // u16 region unused; covers hist(16K)/scan(4K)/rank(32K)/nms(48.9K)
    cudaFuncSetAttribute(k_all, cudaFuncAttributeMaxDynamicSharedMemorySize, smem);
    k_all<<<NCTA, NTH, smem>>>(rpn_class, rpn_bbox, anchors, out);
}

// round 9
// speedup vs baseline: 6.7429x; 1.7998x over previous
#include <cuda_runtime.h>
#include <cuda_bf16.h>

#define BB 4
#define NN 261888
#define NH (NN / 2)
#define PP 6000
#define NP 2000
#define NBINS 65536
#define CAP 16384
#define NW 94          // ceil(PP/64)
#define NWPAD 96       // padded gmem row (16B aligned)
#define SEGCAP 4096
#define DPAD 6016      // NW*64
#define NCTA 148
#define NTH 1024
#define NS 8
#define HBASE 0x3C00   // smem-privatized bins: scores >= 2^-7
#define HSPAN 4096
#define BLK1 40        // speculative NMS window (2560 candidates)

typedef unsigned long long u64;

// ---------------- scratch (device globals; no allocations) ----------------
__device__ unsigned int        g_hist[BB][NBINS];
__device__ unsigned int        g_cursor[BB][NBINS];
__device__ int                 g_thresh[BB];
__device__ unsigned int        g_barrier[NS];     // zero-init; self-resetting
__device__ u64                 g_cand[BB][CAP];
__device__ __align__(16) float4 g_boxes[BB][PP];
__device__ float               g_area[BB][PP];
__device__ __align__(16) u64   g_supp[BB][PP][NWPAD];
__device__ __align__(16) u64   g_diag[BB][PP];
__device__ __align__(16) u64   g_rownz[BB][NW];
__device__ u64                 g_removed[BB][NW];
__device__ u64                 g_keptmask[BB][NW];
__device__ int                 g_done[BB];
__device__ int                 g_base[BB];

__device__ __forceinline__ int hslot(int bin) {
    return ((bin & 31) << 11) | (bin >> 5);
}

// grid barrier over NCTA co-resident CTAs; CTA0 resets slot s-1 after passing s
__device__ __forceinline__ void gbar(int s) {
    __syncthreads();
    if (threadIdx.x == 0) {
        __threadfence();
        atomicAdd(&g_barrier[s], 1u);
        while (((volatile unsigned*)g_barrier)[s] < NCTA) __nanosleep(64);
        __threadfence();
        if (blockIdx.x == 0 && s > 0) atomicExch(&g_barrier[s - 1], 0u);
    }
    __syncthreads();
}

// one tile of the suppression-mask computation
__device__ __forceinline__ void mask_tile(int b, int ib, int jb, int tid,
                                          float4* bj, float* aj) {
    int i = ib * 64 + (tid & 63);
    int j0 = jb * 64;
    if (tid < 64) {
        int jt = j0 + tid;
        if (jt < PP) { bj[tid] = g_boxes[b][jt]; aj[tid] = g_area[b][jt]; }
    }
    __syncthreads();
    if (jb >= ib && i < PP) {
        float4 bi = g_boxes[b][i];
        float  ai = g_area[b][i];
        u64 mask = 0ull;
        int jmax = min(64, PP - j0);
        #pragma unroll 4
        for (int jj = 0; jj < jmax; jj++) {
            if (j0 + jj <= i) continue;
            float4 bx = bj[jj];
            float iy1 = fmaxf(bi.x, bx.x), ix1 = fmaxf(bi.y, bx.y);
            float iy2 = fminf(bi.z, bx.z), ix2 = fminf(bi.w, bx.w);
            float ih = fmaxf(iy2 - iy1, 0.f), iw = fmaxf(ix2 - ix1, 0.f);
            float inter = ih * iw;
            float uni = ai + aj[jj] - inter;
            if (inter > 0.7f * fmaxf(uni, 1e-8f)) mask |= (1ull << jj);
        }
        if (jb == ib) {
            g_diag[b][i] = mask;
        } else {
            g_supp[b][i][jb] = mask;
            if (mask) atomicOr(&g_rownz[b][ib], 1ull << (i & 63));
        }
    }
    __syncthreads();
}

__global__ void __launch_bounds__(NTH, 1)
k_all(const float* __restrict__ rpn_class,
      const float* __restrict__ rpn_bbox,
      const float* __restrict__ anchors,
      float* __restrict__ out) {
    extern __shared__ u64 sh[];
    const int cta = blockIdx.x, tid = threadIdx.x;
    const int gtid = cta * NTH + tid;
    const int GT = NCTA * NTH;
    const int bb = cta & 3, cs = cta >> 2;

    // ---- phase 0: init persistent state; reset terminal barrier slots ----
    if (cta == 0 && tid == 0) { atomicExch(&g_barrier[6], 0u); atomicExch(&g_barrier[7], 0u); }
    for (int x = gtid; x < BB * NBINS; x += GT) ((unsigned*)g_hist)[x] = 0u;
    for (int x = gtid; x < BB * NW; x += GT) ((u64*)g_rownz)[x] = 0ull;
    if (gtid < BB) { g_thresh[gtid] = NBINS; g_done[gtid] = 0; }
    gbar(0);

    // ---- phase 1: histogram (smem-privatized hot bins) ----
    {
        unsigned* hh = (unsigned*)sh;
        for (int x = tid; x < HSPAN; x += NTH) hh[x] = 0u;
        __syncthreads();
        for (int i = cs * NTH + tid; i < NH; i += 37 * NTH) {
            float4 v = *(const float4*)(rpn_class + (size_t)bb * NN * 2 + (size_t)i * 4);
            unsigned b0 = __float_as_uint(v.y) >> 16;
            unsigned b1 = __float_as_uint(v.w) >> 16;
            if (b0 >= HBASE) atomicAdd(&hh[b0 - HBASE], 1u);
            else             atomicAdd(&g_hist[bb][hslot(b0)], 1u);
            if (b1 >= HBASE) atomicAdd(&hh[b1 - HBASE], 1u);
            else             atomicAdd(&g_hist[bb][hslot(b1)], 1u);
        }
        __syncthreads();
        for (int x = tid; x < HSPAN; x += NTH) {
            unsigned c = hh[x];
            if (c) atomicAdd(&g_hist[bb][hslot(HBASE + x)], c);
        }
    }
    gbar(1);

    // ---- phase 2: descending prefix sum, cursor bases, threshold ----
    if (cta < BB) {
        int b = cta;
        unsigned* gs = (unsigned*)sh;
        unsigned s = 0;
        #pragma unroll 8
        for (int k = 0; k < 64; k++) s += g_hist[b][hslot(tid * 64 + k)];
        gs[tid] = s;
        __syncthreads();
        unsigned self = s;
        for (int off = 1; off < 1024; off <<= 1) {
            unsigned v = (tid + off < 1024) ? gs[tid + off] : 0u;
            __syncthreads();
            gs[tid] += v;
            __syncthreads();
        }
        unsigned run = gs[tid] - self;
        int minbin = NBINS;
        for (int k = 63; k >= 0; k--) {
            int bin = tid * 64 + k;
            int hs = hslot(bin);
            g_cursor[b][hs] = run;
            if (run < PP) minbin = bin;
            run += g_hist[b][hs];
        }
        if (minbin < NBINS) atomicMin(&g_thresh[b], minbin);
    }
    gbar(2);

    // ---- phase 3: scatter candidates grouped by bin ----
    {
        int th = g_thresh[bb];
        for (int i = cs * NTH + tid; i < NH; i += 37 * NTH) {
            float4 v = *(const float4*)(rpn_class + (size_t)bb * NN * 2 + (size_t)i * 4);
            unsigned bits0 = __float_as_uint(v.y);
            unsigned bits1 = __float_as_uint(v.w);
            if ((int)(bits0 >> 16) >= th) {
                unsigned pos = atomicAdd(&g_cursor[bb][hslot(bits0 >> 16)], 1u);
                if (pos < CAP)
                    g_cand[bb][pos] = ((u64)bits0 << 32) | (u64)(0xFFFFFFFFu - (unsigned)(2 * i));
            }
            if ((int)(bits1 >> 16) >= th) {
                unsigned pos = atomicAdd(&g_cursor[bb][hslot(bits1 >> 16)], 1u);
                if (pos < CAP)
                    g_cand[bb][pos] = ((u64)bits1 << 32) | (u64)(0xFFFFFFFFu - (unsigned)(2 * i + 1));
            }
        }
    }
    gbar(3);

    // ---- phase 4: per-bin rank-by-count + fused decode ----
    for (int slot = cta; slot < BB * 64; slot += NCTA) {
        int b = slot >> 6, binoff = slot & 63;
        int bin = g_thresh[b] + binoff;
        if (bin >= NBINS) continue;
        int hs = hslot(bin);
        unsigned cnt = g_hist[b][hs];
        if (cnt == 0) continue;
        unsigned base = g_cursor[b][hs] - cnt;
        if (base >= PP) continue;
        unsigned cc = cnt < (unsigned)SEGCAP ? cnt : (unsigned)SEGCAP;
        u64* key = sh;
        for (unsigned x = tid; x < cc; x += NTH) key[x] = g_cand[b][base + x];
        __syncthreads();
        for (unsigned x = tid; x < cc; x += NTH) {
            u64 me = key[x];
            unsigned rank = 0;
            for (unsigned y = 0; y < cc; y++) rank += (key[y] > me);
            unsigned p = base + rank;
            if (p >= PP) continue;
            unsigned idx = 0xFFFFFFFFu - (unsigned)(me & 0xFFFFFFFFull);
            float4 a = *(const float4*)(anchors + (size_t)idx * 4);
            float4 d = *(const float4*)(rpn_bbox + ((size_t)b * NN + idx) * 4);
            d.x *= 0.1f; d.y *= 0.1f; d.z *= 0.2f; d.w *= 0.2f;
            float h = a.z - a.x, w = a.w - a.y;
            float cy = a.x + 0.5f * h, cx = a.y + 0.5f * w;
            cy = cy + d.x * h;
            cx = cx + d.y * w;
            h = h * expf(d.z);
            w = w * expf(d.w);
            float y1 = cy - 0.5f * h, x1 = cx - 0.5f * w;
            float y2 = cy + 0.5f * h, x2 = cx + 0.5f * w;
            y1 = fminf(fmaxf(y1, 0.f), 1024.f);
            x1 = fminf(fmaxf(x1, 0.f), 1024.f);
            y2 = fminf(fmaxf(y2, 0.f), 1024.f);
            x2 = fminf(fmaxf(x2, 0.f), 1024.f);
            const float inv = 1.0f / 1024.0f;
            float4 o = make_float4(y1 * inv, x1 * inv, y2 * inv, x2 * inv);
            g_boxes[b][p] = o;
            g_area[b][p] = (o.z - o.x) * (o.w - o.y);
        }
        __syncthreads();
    }
    gbar(4);

    // ---- phase 5a: mask tiles for the speculative window (ib<=jb<BLK1) ----
    {
        float4* bj = (float4*)sh;
        float*  aj = (float*)(bj + 64);
        const int NIBG1 = (BLK1 + 15) / 16;           // 3
        const int PER_B = BLK1 * NIBG1;               // 120
        for (int st = cta; st < BB * PER_B; st += NCTA) {
            int b = st / PER_B;
            int r = st % PER_B;
            int jb = r / NIBG1, ibg = r % NIBG1;
            if (jb < ibg * 16) continue;
            mask_tile(b, ibg * 16 + (tid >> 6), jb, tid, bj, aj);
        }
    }
    gbar(5);

    // ---- phase 6a: speculative NMS over blocks [0, BLK1) ----
    if (cta < BB) {
        int b = cta;
        u64* s_diag = sh;
        u64* s_rownz = sh + DPAD;
        __shared__ u64 s_pre, s_kept;
        __shared__ unsigned s_nz[2];
        __shared__ int s_base, s_prev, s_stop;

        float4* ob = (float4*)(out + (size_t)b * NP * 4);
        for (int x = tid; x < NP; x += NTH) ob[x] = make_float4(0.f, 0.f, 0.f, 0.f);
        for (int x = tid; x < BLK1 * 64; x += NTH) s_diag[x] = g_diag[b][x];
        for (int x = tid; x < NW; x += NTH) s_rownz[x] = g_rownz[b][x];

        u64 acc = 0ull;
        if (tid == 0) { s_base = 0; s_stop = 0; }
        __syncthreads();

        for (int blk = 0; blk < BLK1; blk++) {
            if (tid < 64) {
                u64 d = s_diag[blk * 64 + tid];
                unsigned bal = __ballot_sync(0xffffffffu, d != 0ull);
                if ((tid & 31) == 0) s_nz[tid >> 5] = bal;
            }
            if (tid == blk) s_pre = acc;
            __syncthreads();

            if (tid == 0) {
                u64 jm = (u64)s_nz[0] | ((u64)s_nz[1] << 32);
                u64 alive = ~s_pre;
                while (jm) {
                    int j = __ffsll((long long)jm) - 1; jm &= jm - 1;
                    if ((alive >> j) & 1ull) alive &= ~s_diag[blk * 64 + j];
                }
                int cnt = __popcll(alive);
                int rem = NP - s_base;
                while (cnt > rem) {
                    alive &= ~(1ull << (63 - __clzll((long long)alive)));
                    cnt--;
                }
                s_kept = alive;
                g_keptmask[b][blk] = alive;
                s_prev = s_base;
                s_base += cnt;
                if (s_base >= NP) s_stop = 1;
            }
            __syncthreads();

            u64 km = s_kept;
            if (tid < 64 && ((km >> tid) & 1ull)) {
                u64 lowmask = (tid == 0) ? 0ull : (km & ((1ull << tid) - 1ull));
                ob[s_prev + __popcll(lowmask)] = g_boxes[b][blk * 64 + tid];
            }
            if (tid < BLK1 && tid > blk) {            // only columns < BLK1 are valid
                u64 nz = s_rownz[blk] & km;
                while (nz) {
                    int j = __ffsll((long long)nz) - 1; nz &= nz - 1;
                    acc |= g_supp[b][blk * 64 + j][tid];
                }
            }
            if (s_stop) break;
        }
        __syncthreads();
        if (tid < NW) g_removed[b][tid] = acc;        // tid>=BLK1 words are 0 (placeholder)
        if (tid == 0) { g_done[b] = s_stop; g_base[b] = s_base; }
    }
    gbar(6);

    // ---- all-done check (uniform across CTAs) ----
    {
        __shared__ int s_alldone;
        if (tid == 0)
            s_alldone = g_done[0] & g_done[1] & g_done[2] & g_done[3];
        __syncthreads();
        if (s_alldone) return;                        // common case
    }

    // ---- phase 7: remaining mask tiles (jb >= BLK1, ib <= jb) ----
    {
        float4* bj = (float4*)sh;
        float*  aj = (float*)(bj + 64);
        const int NIBG = (NW + 15) / 16;              // 6
        const int PER_B = (NW - BLK1) * NIBG;         // 324
        for (int st = cta; st < BB * PER_B; st += NCTA) {
            int b = st / PER_B;
            int r = st % PER_B;
            int jb = BLK1 + r / NIBG, ibg = r % NIBG;
            if (jb < ibg * 16) continue;
            mask_tile(b, ibg * 16 + (tid >> 6), jb, tid, bj, aj);
        }
    }
    gbar(7);
    if (cta >= BB) return;

    // ---- phase 8: NMS continuation over blocks [BLK1, NW) ----
    {
        int b = cta;
        u64* s_diag = sh;
        u64* s_rownz = sh + DPAD;
        __shared__ u64 s_pre, s_kept;
        __shared__ unsigned s_nz[2];
        __shared__ int s_base, s_prev, s_stop;

        float4* ob = (float4*)(out + (size_t)b * NP * 4);
        for (int x = tid; x < DPAD; x += NTH)
            s_diag[x] = (x < PP) ? g_diag[b][x] : 0ull;
        for (int x = tid; x < NW; x += NTH) s_rownz[x] = g_rownz[b][x];
        if (tid == 0) { s_base = g_base[b]; s_stop = g_done[b]; }
        __syncthreads();

        u64 acc = (tid < NW) ? g_removed[b][tid] : 0ull;
        if (tid >= BLK1 && tid < NW) {                // reconstruct high words
            for (int blk = 0; blk < BLK1; blk++) {
                u64 nz = s_rownz[blk] & g_keptmask[b][blk];
                while (nz) {
                    int j = __ffsll((long long)nz) - 1; nz &= nz - 1;
                    acc |= g_supp[b][blk * 64 + j][tid];
                }
            }
        }
        __syncthreads();

        for (int blk = BLK1; blk < NW && !s_stop; blk++) {
            if (tid < 64) {
                u64 d = s_diag[blk * 64 + tid];
                unsigned bal = __ballot_sync(0xffffffffu, d != 0ull);
                if ((tid & 31) == 0) s_nz[tid >> 5] = bal;
            }
            if (tid == blk) s_pre = acc;
            __syncthreads();

            if (tid == 0) {
                u64 jm = (u64)s_nz[0] | ((u64)s_nz[1] << 32);
                u64 alive = ~s_pre;
                if (blk == NW - 1) alive &= (1ull << (PP - (NW - 1) * 64)) - 1ull;
                while (jm) {
                    int j = __ffsll((long long)jm) - 1; jm &= jm - 1;
                    if ((alive >> j) & 1ull) alive &= ~s_diag[blk * 64 + j];
                }
                int cnt = __popcll(alive);
                int rem = NP - s_base;
                while (cnt > rem) {
                    alive &= ~(1ull << (63 - __clzll((long long)alive)));
                    cnt--;
                }
                s_kept = alive;
                s_prev = s_base;
                s_base += cnt;
                if (s_base >= NP) s_stop = 1;
            }
            __syncthreads();

            u64 km = s_kept;
            if (tid < 64 && ((km >> tid) & 1ull)) {
                u64 lowmask = (tid == 0) ? 0ull : (km & ((1ull << tid) - 1ull));
                ob[s_prev + __popcll(lowmask)] = g_boxes[b][blk * 64 + tid];
            }
            if (tid < NW && tid > blk) {
                u64 nz = s_rownz[blk] & km;
                while (nz) {
                    int j = __ffsll((long long)nz) - 1; nz &= nz - 1;
                    acc |= g_supp[b][blk * 64 + j][tid];
                }
            }
            __syncthreads();
        }
    }
}

// ---------------- launch ----------------
extern "C" void kernel_launch(void* const* d_in, const int* in_sizes, int n_in,
                              void* d_out, int out_size) {
    const float* rpn_class = (const float*)d_in[0];
    const float* rpn_bbox  = (const float*)d_in[1];
    const float* anchors   = (const float*)d_in[2];
    float* out = (float*)d_out;

    int smem = 131072;
    cudaFuncSetAttribute(k_all, cudaFuncAttributeMaxDynamicSharedMemorySize, smem);
    k_all<<<NCTA, NTH, smem>>>(rpn_class, rpn_bbox, anchors, out);
}

// round 10
// speedup vs baseline: 6.8918x; 1.0221x over previous
#include <cuda_runtime.h>
#include <cuda_bf16.h>

#define BB 4
#define NN 261888
#define NH (NN / 2)
#define PP 6000
#define NP 2000
#define NBINS 65536
#define CAP 16384
#define NW 94          // ceil(PP/64)
#define NWPAD 96       // padded gmem row (16B aligned)
#define SEGCAP 4096
#define DPAD 6016      // NW*64
#define NCTA 148
#define NTH 1024
#define NS 8
#define HBASE 0x3C00   // smem-privatized bins: scores >= 2^-7
#define HSPAN 4096
#define BLK1 40        // speculative NMS window (2560 candidates)

typedef unsigned long long u64;

// ---------------- scratch (device globals; no allocations) ----------------
__device__ unsigned int        g_hist[BB][NBINS];
__device__ unsigned int        g_cursor[BB][NBINS];
__device__ int                 g_thresh[BB];
__device__ unsigned int        g_barrier[NS];     // zero-init; self-resetting
__device__ u64                 g_cand[BB][CAP];
__device__ __align__(16) float4 g_boxes[BB][PP];
__device__ float               g_area[BB][PP];
__device__ __align__(16) u64   g_supp[BB][PP][NWPAD];
__device__ __align__(16) u64   g_diag[BB][PP];
__device__ __align__(16) u64   g_rownz[BB][NW];
__device__ u64                 g_removed[BB][NW];
__device__ u64                 g_keptmask[BB][NW];
__device__ int                 g_done[BB];
__device__ int                 g_base[BB];

__device__ __forceinline__ int hslot(int bin) {
    return ((bin & 31) << 11) | (bin >> 5);
}

// grid barrier over NCTA co-resident CTAs; CTA0 resets slot s-1 after passing s
__device__ __forceinline__ void gbar(int s) {
    __syncthreads();
    if (threadIdx.x == 0) {
        __threadfence();
        atomicAdd(&g_barrier[s], 1u);
        while (((volatile unsigned*)g_barrier)[s] < NCTA) __nanosleep(64);
        __threadfence();
        if (blockIdx.x == 0 && s > 0) atomicExch(&g_barrier[s - 1], 0u);
    }
    __syncthreads();
}

// one tile of the suppression-mask computation
__device__ __forceinline__ void mask_tile(int b, int ib, int jb, int tid,
                                          float4* bj, float* aj) {
    int i = ib * 64 + (tid & 63);
    int j0 = jb * 64;
    if (tid < 64) {
        int jt = j0 + tid;
        if (jt < PP) { bj[tid] = g_boxes[b][jt]; aj[tid] = g_area[b][jt]; }
    }
    __syncthreads();
    if (jb >= ib && i < PP) {
        float4 bi = g_boxes[b][i];
        float  ai = g_area[b][i];
        u64 mask = 0ull;
        int jmax = min(64, PP - j0);
        #pragma unroll 4
        for (int jj = 0; jj < jmax; jj++) {
            if (j0 + jj <= i) continue;
            float4 bx = bj[jj];
            float iy1 = fmaxf(bi.x, bx.x), ix1 = fmaxf(bi.y, bx.y);
            float iy2 = fminf(bi.z, bx.z), ix2 = fminf(bi.w, bx.w);
            float ih = fmaxf(iy2 - iy1, 0.f), iw = fmaxf(ix2 - ix1, 0.f);
            float inter = ih * iw;
            float uni = ai + aj[jj] - inter;
            if (inter > 0.7f * fmaxf(uni, 1e-8f)) mask |= (1ull << jj);
        }
        if (jb == ib) {
            g_diag[b][i] = mask;
        } else {
            g_supp[b][i][jb] = mask;
            if (mask) atomicOr(&g_rownz[b][ib], 1ull << (i & 63));
        }
    }
    __syncthreads();
}

__global__ void __launch_bounds__(NTH, 1)
k_all(const float* __restrict__ rpn_class,
      const float* __restrict__ rpn_bbox,
      const float* __restrict__ anchors,
      float* __restrict__ out) {
    extern __shared__ u64 sh[];
    const int cta = blockIdx.x, tid = threadIdx.x;
    const int gtid = cta * NTH + tid;
    const int GT = NCTA * NTH;
    const int bb = cta & 3, cs = cta >> 2;

    // ---- phase 0: init persistent state; reset terminal barrier slots ----
    if (cta == 0 && tid == 0) { atomicExch(&g_barrier[6], 0u); atomicExch(&g_barrier[7], 0u); }
    for (int x = gtid; x < BB * NBINS; x += GT) ((unsigned*)g_hist)[x] = 0u;
    for (int x = gtid; x < BB * NW; x += GT) ((u64*)g_rownz)[x] = 0ull;
    if (gtid < BB) { g_thresh[gtid] = NBINS; g_done[gtid] = 0; }
    gbar(0);

    // ---- phase 1: histogram (smem-privatized hot bins) ----
    {
        unsigned* hh = (unsigned*)sh;
        for (int x = tid; x < HSPAN; x += NTH) hh[x] = 0u;
        __syncthreads();
        for (int i = cs * NTH + tid; i < NH; i += 37 * NTH) {
            float4 v = *(const float4*)(rpn_class + (size_t)bb * NN * 2 + (size_t)i * 4);
            unsigned b0 = __float_as_uint(v.y) >> 16;
            unsigned b1 = __float_as_uint(v.w) >> 16;
            if (b0 >= HBASE) atomicAdd(&hh[b0 - HBASE], 1u);
            else             atomicAdd(&g_hist[bb][hslot(b0)], 1u);
            if (b1 >= HBASE) atomicAdd(&hh[b1 - HBASE], 1u);
            else             atomicAdd(&g_hist[bb][hslot(b1)], 1u);
        }
        __syncthreads();
        for (int x = tid; x < HSPAN; x += NTH) {
            unsigned c = hh[x];
            if (c) atomicAdd(&g_hist[bb][hslot(HBASE + x)], c);
        }
    }
    gbar(1);

    // ---- phase 2: descending prefix sum, cursor bases, threshold ----
    if (cta < BB) {
        int b = cta;
        unsigned* gs = (unsigned*)sh;
        unsigned s = 0;
        #pragma unroll 8
        for (int k = 0; k < 64; k++) s += g_hist[b][hslot(tid * 64 + k)];
        gs[tid] = s;
        __syncthreads();
        unsigned self = s;
        for (int off = 1; off < 1024; off <<= 1) {
            unsigned v = (tid + off < 1024) ? gs[tid + off] : 0u;
            __syncthreads();
            gs[tid] += v;
            __syncthreads();
        }
        unsigned run = gs[tid] - self;
        int minbin = NBINS;
        for (int k = 63; k >= 0; k--) {
            int bin = tid * 64 + k;
            int hs = hslot(bin);
            g_cursor[b][hs] = run;
            if (run < PP) minbin = bin;
            run += g_hist[b][hs];
        }
        if (minbin < NBINS) atomicMin(&g_thresh[b], minbin);
    }
    gbar(2);

    // ---- phase 3: scatter candidates grouped by bin ----
    {
        int th = g_thresh[bb];
        for (int i = cs * NTH + tid; i < NH; i += 37 * NTH) {
            float4 v = *(const float4*)(rpn_class + (size_t)bb * NN * 2 + (size_t)i * 4);
            unsigned bits0 = __float_as_uint(v.y);
            unsigned bits1 = __float_as_uint(v.w);
            if ((int)(bits0 >> 16) >= th) {
                unsigned pos = atomicAdd(&g_cursor[bb][hslot(bits0 >> 16)], 1u);
                if (pos < CAP)
                    g_cand[bb][pos] = ((u64)bits0 << 32) | (u64)(0xFFFFFFFFu - (unsigned)(2 * i));
            }
            if ((int)(bits1 >> 16) >= th) {
                unsigned pos = atomicAdd(&g_cursor[bb][hslot(bits1 >> 16)], 1u);
                if (pos < CAP)
                    g_cand[bb][pos] = ((u64)bits1 << 32) | (u64)(0xFFFFFFFFu - (unsigned)(2 * i + 1));
            }
        }
    }
    gbar(3);

    // ---- phase 4: per-bin rank-by-count + fused decode ----
    for (int slot = cta; slot < BB * 64; slot += NCTA) {
        int b = slot >> 6, binoff = slot & 63;
        int bin = g_thresh[b] + binoff;
        if (bin >= NBINS) continue;
        int hs = hslot(bin);
        unsigned cnt = g_hist[b][hs];
        if (cnt == 0) continue;
        unsigned base = g_cursor[b][hs] - cnt;
        if (base >= PP) continue;
        unsigned cc = cnt < (unsigned)SEGCAP ? cnt : (unsigned)SEGCAP;
        u64* key = sh;
        for (unsigned x = tid; x < cc; x += NTH) key[x] = g_cand[b][base + x];
        __syncthreads();
        for (unsigned x = tid; x < cc; x += NTH) {
            u64 me = key[x];
            unsigned rank = 0;
            for (unsigned y = 0; y < cc; y++) rank += (key[y] > me);
            unsigned p = base + rank;
            if (p >= PP) continue;
            unsigned idx = 0xFFFFFFFFu - (unsigned)(me & 0xFFFFFFFFull);
            float4 a = *(const float4*)(anchors + (size_t)idx * 4);
            float4 d = *(const float4*)(rpn_bbox + ((size_t)b * NN + idx) * 4);
            d.x *= 0.1f; d.y *= 0.1f; d.z *= 0.2f; d.w *= 0.2f;
            float h = a.z - a.x, w = a.w - a.y;
            float cy = a.x + 0.5f * h, cx = a.y + 0.5f * w;
            cy = cy + d.x * h;
            cx = cx + d.y * w;
            h = h * expf(d.z);
            w = w * expf(d.w);
            float y1 = cy - 0.5f * h, x1 = cx - 0.5f * w;
            float y2 = cy + 0.5f * h, x2 = cx + 0.5f * w;
            y1 = fminf(fmaxf(y1, 0.f), 1024.f);
            x1 = fminf(fmaxf(x1, 0.f), 1024.f);
            y2 = fminf(fmaxf(y2, 0.f), 1024.f);
            x2 = fminf(fmaxf(x2, 0.f), 1024.f);
            const float inv = 1.0f / 1024.0f;
            float4 o = make_float4(y1 * inv, x1 * inv, y2 * inv, x2 * inv);
            g_boxes[b][p] = o;
            g_area[b][p] = (o.z - o.x) * (o.w - o.y);
        }
        __syncthreads();
    }
    gbar(4);

    // ---- phase 5a: mask tiles for the speculative window (ib<=jb<BLK1) ----
    {
        float4* bj = (float4*)sh;
        float*  aj = (float*)(bj + 64);
        const int NIBG1 = (BLK1 + 15) / 16;           // 3
        const int PER_B = BLK1 * NIBG1;               // 120
        for (int st = cta; st < BB * PER_B; st += NCTA) {
            int b = st / PER_B;
            int r = st % PER_B;
            int jb = r / NIBG1, ibg = r % NIBG1;
            if (jb < ibg * 16) continue;
            mask_tile(b, ibg * 16 + (tid >> 6), jb, tid, bj, aj);
        }
    }
    gbar(5);

    // ---- phase 6a: speculative NMS over blocks [0, BLK1) ----
    if (cta < BB) {
        int b = cta;
        u64* s_diag = sh;
        u64* s_rownz = sh + DPAD;
        __shared__ u64 s_pre, s_kept;
        __shared__ unsigned s_nz[2];
        __shared__ int s_base, s_prev, s_stop;

        float4* ob = (float4*)(out + (size_t)b * NP * 4);
        for (int x = tid; x < NP; x += NTH) ob[x] = make_float4(0.f, 0.f, 0.f, 0.f);
        for (int x = tid; x < BLK1 * 64; x += NTH) s_diag[x] = g_diag[b][x];
        for (int x = tid; x < NW; x += NTH) s_rownz[x] = g_rownz[b][x];

        u64 acc = 0ull;
        if (tid == 0) { s_base = 0; s_stop = 0; }
        __syncthreads();

        for (int blk = 0; blk < BLK1; blk++) {
            if (tid < 64) {
                u64 d = s_diag[blk * 64 + tid];
                unsigned bal = __ballot_sync(0xffffffffu, d != 0ull);
                if ((tid & 31) == 0) s_nz[tid >> 5] = bal;
            }
            if (tid == blk) s_pre = acc;
            __syncthreads();

            if (tid == 0) {
                u64 jm = (u64)s_nz[0] | ((u64)s_nz[1] << 32);
                u64 alive = ~s_pre;
                while (jm) {
                    int j = __ffsll((long long)jm) - 1; jm &= jm - 1;
                    if ((alive >> j) & 1ull) alive &= ~s_diag[blk * 64 + j];
                }
                int cnt = __popcll(alive);
                int rem = NP - s_base;
                while (cnt > rem) {
                    alive &= ~(1ull << (63 - __clzll((long long)alive)));
                    cnt--;
                }
                s_kept = alive;
                g_keptmask[b][blk] = alive;
                s_prev = s_base;
                s_base += cnt;
                if (s_base >= NP) s_stop = 1;
            }
            __syncthreads();

            u64 km = s_kept;
            if (tid < 64 && ((km >> tid) & 1ull)) {
                u64 lowmask = (tid == 0) ? 0ull : (km & ((1ull << tid) - 1ull));
                ob[s_prev + __popcll(lowmask)] = g_boxes[b][blk * 64 + tid];
            }
            if (tid < BLK1 && tid > blk) {            // only columns < BLK1 are valid
                u64 nz = s_rownz[blk] & km;
                while (nz) {
                    int j = __ffsll((long long)nz) - 1; nz &= nz - 1;
                    acc |= g_supp[b][blk * 64 + j][tid];
                }
            }
            if (s_stop) break;
        }
        __syncthreads();
        if (tid < NW) g_removed[b][tid] = acc;        // tid>=BLK1 words are 0 (placeholder)
        if (tid == 0) { g_done[b] = s_stop; g_base[b] = s_base; }
    }
    gbar(6);

    // ---- all-done check (uniform across CTAs) ----
    {
        __shared__ int s_alldone;
        if (tid == 0)
            s_alldone = g_done[0] & g_done[1] & g_done[2] & g_done[3];
        __syncthreads();
        if (s_alldone) return;                        // common case
    }

    // ---- phase 7: remaining mask tiles (jb >= BLK1, ib <= jb) ----
    {
        float4* bj = (float4*)sh;
        float*  aj = (float*)(bj + 64);
        const int NIBG = (NW + 15) / 16;              // 6
        const int PER_B = (NW - BLK1) * NIBG;         // 324
        for (int st = cta; st < BB * PER_B; st += NCTA) {
            int b = st / PER_B;
            int r = st % PER_B;
            int jb = BLK1 + r / NIBG, ibg = r % NIBG;
            if (jb < ibg * 16) continue;
            mask_tile(b, ibg * 16 + (tid >> 6), jb, tid, bj, aj);
        }
    }
    gbar(7);
    if (cta >= BB) return;

    // ---- phase 8: NMS continuation over blocks [BLK1, NW) ----
    {
        int b = cta;
        u64* s_diag = sh;
        u64* s_rownz = sh + DPAD;
        __shared__ u64 s_pre, s_kept;
        __shared__ unsigned s_nz[2];
        __shared__ int s_base, s_prev, s_stop;

        float4* ob = (float4*)(out + (size_t)b * NP * 4);
        for (int x = tid; x < DPAD; x += NTH)
            s_diag[x] = (x < PP) ? g_diag[b][x] : 0ull;
        for (int x = tid; x < NW; x += NTH) s_rownz[x] = g_rownz[b][x];
        if (tid == 0) { s_base = g_base[b]; s_stop = g_done[b]; }
        __syncthreads();

        u64 acc = (tid < NW) ? g_removed[b][tid] : 0ull;
        if (tid >= BLK1 && tid < NW) {                // reconstruct high words
            for (int blk = 0; blk < BLK1; blk++) {
                u64 nz = s_rownz[blk] & g_keptmask[b][blk];
                while (nz) {
                    int j = __ffsll((long long)nz) - 1; nz &= nz - 1;
                    acc |= g_supp[b][blk * 64 + j][tid];
                }
            }
        }
        __syncthreads();

        for (int blk = BLK1; blk < NW && !s_stop; blk++) {
            if (tid < 64) {
                u64 d = s_diag[blk * 64 + tid];
                unsigned bal = __ballot_sync(0xffffffffu, d != 0ull);
                if ((tid & 31) == 0) s_nz[tid >> 5] = bal;
            }
            if (tid == blk) s_pre = acc;
            __syncthreads();

            if (tid == 0) {
                u64 jm = (u64)s_nz[0] | ((u64)s_nz[1] << 32);
                u64 alive = ~s_pre;
                if (blk == NW - 1) alive &= (1ull << (PP - (NW - 1) * 64)) - 1ull;
                while (jm) {
                    int j = __ffsll((long long)jm) - 1; jm &= jm - 1;
                    if ((alive >> j) & 1ull) alive &= ~s_diag[blk * 64 + j];
                }
                int cnt = __popcll(alive);
                int rem = NP - s_base;
                while (cnt > rem) {
                    alive &= ~(1ull << (63 - __clzll((long long)alive)));
                    cnt--;
                }
                s_kept = alive;
                s_prev = s_base;
                s_base += cnt;
                if (s_base >= NP) s_stop = 1;
            }
            __syncthreads();

            u64 km = s_kept;
            if (tid < 64 && ((km >> tid) & 1ull)) {
                u64 lowmask = (tid == 0) ? 0ull : (km & ((1ull << tid) - 1ull));
                ob[s_prev + __popcll(lowmask)] = g_boxes[b][blk * 64 + tid];
            }
            if (tid < NW && tid > blk) {
                u64 nz = s_rownz[blk] & km;
                while (nz) {
                    int j = __ffsll((long long)nz) - 1; nz &= nz - 1;
                    acc |= g_supp[b][blk * 64 + j][tid];
                }
            }
            __syncthreads();
        }
    }
}

// ---------------- launch ----------------
extern "C" void kernel_launch(void* const* d_in, const int* in_sizes, int n_in,
                              void* d_out, int out_size) {
    const float* rpn_class = (const float*)d_in[0];
    const float* rpn_bbox  = (const float*)d_in[1];
    const float* anchors   = (const float*)d_in[2];
    float* out = (float*)d_out;

    int smem = 131072;
    cudaFuncSetAttribute(k_all, cudaFuncAttributeMaxDynamicSharedMemorySize, smem);
    k_all<<<NCTA, NTH, smem>>>(rpn_class, rpn_bbox, anchors, out);
}

// round 11
// speedup vs baseline: 6.9446x; 1.0077x over previous
#include <cuda_runtime.h>
#include <cuda_bf16.h>

#define BB 4
#define NN 261888
#define NH (NN / 2)
#define PP 6000
#define NP 2000
#define NBINS 65536
#define CAP 16384
#define NW 94          // ceil(PP/64)
#define NWPAD 96       // padded gmem row (16B aligned)
#define SEGCAP 4096
#define DPAD 6016      // NW*64
#define NCTA 148
#define NTH 1024
#define NS 8
#define HBASE 0x3C00   // smem-privatized bins: scores >= 2^-7
#define HSPAN 4096
#define BLK1 40        // speculative NMS window (2560 candidates)

typedef unsigned long long u64;

// ---------------- scratch (device globals; no allocations) ----------------
__device__ unsigned int        g_hist[BB][NBINS];
__device__ unsigned int        g_cursor[BB][NBINS];
__device__ int                 g_thresh[BB];
__device__ unsigned int        g_barrier[NS];     // zero-init; self-resetting
__device__ u64                 g_cand[BB][CAP];
__device__ __align__(16) float4 g_boxes[BB][PP];
__device__ float               g_area[BB][PP];
__device__ __align__(16) u64   g_supp[BB][PP][NWPAD];
__device__ __align__(16) u64   g_diag[BB][PP];
__device__ __align__(16) u64   g_rownz[BB][NW];
__device__ u64                 g_removed[BB][NW];
__device__ u64                 g_keptmask[BB][NW];
__device__ int                 g_done[BB];
__device__ int                 g_base[BB];

__device__ __forceinline__ int hslot(int bin) {
    return ((bin & 31) << 11) | (bin >> 5);
}

// grid barrier over NCTA co-resident CTAs; CTA0 resets slot s-1 after passing s
__device__ __forceinline__ void gbar(int s) {
    __syncthreads();
    if (threadIdx.x == 0) {
        __threadfence();
        atomicAdd(&g_barrier[s], 1u);
        while (((volatile unsigned*)g_barrier)[s] < NCTA) __nanosleep(64);
        __threadfence();
        if (blockIdx.x == 0 && s > 0) atomicExch(&g_barrier[s - 1], 0u);
    }
    __syncthreads();
}

// one tile of the suppression-mask computation
__device__ __forceinline__ void mask_tile(int b, int ib, int jb, int tid,
                                          float4* bj, float* aj) {
    int i = ib * 64 + (tid & 63);
    int j0 = jb * 64;
    if (tid < 64) {
        int jt = j0 + tid;
        if (jt < PP) { bj[tid] = g_boxes[b][jt]; aj[tid] = g_area[b][jt]; }
    }
    __syncthreads();
    if (jb >= ib && i < PP) {
        float4 bi = g_boxes[b][i];
        float  ai = g_area[b][i];
        u64 mask = 0ull;
        int jmax = min(64, PP - j0);
        #pragma unroll 4
        for (int jj = 0; jj < jmax; jj++) {
            if (j0 + jj <= i) continue;
            float4 bx = bj[jj];
            float iy1 = fmaxf(bi.x, bx.x), ix1 = fmaxf(bi.y, bx.y);
            float iy2 = fminf(bi.z, bx.z), ix2 = fminf(bi.w, bx.w);
            float ih = fmaxf(iy2 - iy1, 0.f), iw = fmaxf(ix2 - ix1, 0.f);
            float inter = ih * iw;
            float uni = ai + aj[jj] - inter;
            if (inter > 0.7f * fmaxf(uni, 1e-8f)) mask |= (1ull << jj);
        }
        if (jb == ib) {
            g_diag[b][i] = mask;
        } else {
            g_supp[b][i][jb] = mask;
            if (mask) atomicOr(&g_rownz[b][ib], 1ull << (i & 63));
        }
    }
    __syncthreads();
}

__global__ void __launch_bounds__(NTH, 1)
k_all(const float* __restrict__ rpn_class,
      const float* __restrict__ rpn_bbox,
      const float* __restrict__ anchors,
      float* __restrict__ out) {
    extern __shared__ u64 sh[];
    const int cta = blockIdx.x, tid = threadIdx.x;
    const int gtid = cta * NTH + tid;
    const int GT = NCTA * NTH;
    const int bb = cta & 3, cs = cta >> 2;

    // ---- phase 0: init persistent state; reset terminal barrier slots ----
    if (cta == 0 && tid == 0) { atomicExch(&g_barrier[6], 0u); atomicExch(&g_barrier[7], 0u); }
    for (int x = gtid; x < BB * NBINS; x += GT) ((unsigned*)g_hist)[x] = 0u;
    for (int x = gtid; x < BB * NW; x += GT) ((u64*)g_rownz)[x] = 0ull;
    if (gtid < BB) { g_thresh[gtid] = NBINS; g_done[gtid] = 0; }
    gbar(0);

    // ---- phase 1: histogram (smem-privatized hot bins) ----
    {
        unsigned* hh = (unsigned*)sh;
        for (int x = tid; x < HSPAN; x += NTH) hh[x] = 0u;
        __syncthreads();
        for (int i = cs * NTH + tid; i < NH; i += 37 * NTH) {
            float4 v = *(const float4*)(rpn_class + (size_t)bb * NN * 2 + (size_t)i * 4);
            unsigned b0 = __float_as_uint(v.y) >> 16;
            unsigned b1 = __float_as_uint(v.w) >> 16;
            if (b0 >= HBASE) atomicAdd(&hh[b0 - HBASE], 1u);
            else             atomicAdd(&g_hist[bb][hslot(b0)], 1u);
            if (b1 >= HBASE) atomicAdd(&hh[b1 - HBASE], 1u);
            else             atomicAdd(&g_hist[bb][hslot(b1)], 1u);
        }
        __syncthreads();
        for (int x = tid; x < HSPAN; x += NTH) {
            unsigned c = hh[x];
            if (c) atomicAdd(&g_hist[bb][hslot(HBASE + x)], c);
        }
    }
    gbar(1);

    // ---- phase 2: descending prefix sum, cursor bases, threshold ----
    if (cta < BB) {
        int b = cta;
        unsigned* gs = (unsigned*)sh;
        unsigned s = 0;
        #pragma unroll 8
        for (int k = 0; k < 64; k++) s += g_hist[b][hslot(tid * 64 + k)];
        gs[tid] = s;
        __syncthreads();
        unsigned self = s;
        for (int off = 1; off < 1024; off <<= 1) {
            unsigned v = (tid + off < 1024) ? gs[tid + off] : 0u;
            __syncthreads();
            gs[tid] += v;
            __syncthreads();
        }
        unsigned run = gs[tid] - self;
        int minbin = NBINS;
        for (int k = 63; k >= 0; k--) {
            int bin = tid * 64 + k;
            int hs = hslot(bin);
            g_cursor[b][hs] = run;
            if (run < PP) minbin = bin;
            run += g_hist[b][hs];
        }
        if (minbin < NBINS) atomicMin(&g_thresh[b], minbin);
    }
    gbar(2);

    // ---- phase 3: scatter candidates grouped by bin ----
    {
        int th = g_thresh[bb];
        for (int i = cs * NTH + tid; i < NH; i += 37 * NTH) {
            float4 v = *(const float4*)(rpn_class + (size_t)bb * NN * 2 + (size_t)i * 4);
            unsigned bits0 = __float_as_uint(v.y);
            unsigned bits1 = __float_as_uint(v.w);
            if ((int)(bits0 >> 16) >= th) {
                unsigned pos = atomicAdd(&g_cursor[bb][hslot(bits0 >> 16)], 1u);
                if (pos < CAP)
                    g_cand[bb][pos] = ((u64)bits0 << 32) | (u64)(0xFFFFFFFFu - (unsigned)(2 * i));
            }
            if ((int)(bits1 >> 16) >= th) {
                unsigned pos = atomicAdd(&g_cursor[bb][hslot(bits1 >> 16)], 1u);
                if (pos < CAP)
                    g_cand[bb][pos] = ((u64)bits1 << 32) | (u64)(0xFFFFFFFFu - (unsigned)(2 * i + 1));
            }
        }
    }
    gbar(3);

    // ---- phase 4: per-bin rank-by-count + fused decode ----
    for (int slot = cta; slot < BB * 64; slot += NCTA) {
        int b = slot >> 6, binoff = slot & 63;
        int bin = g_thresh[b] + binoff;
        if (bin >= NBINS) continue;
        int hs = hslot(bin);
        unsigned cnt = g_hist[b][hs];
        if (cnt == 0) continue;
        unsigned base = g_cursor[b][hs] - cnt;
        if (base >= PP) continue;
        unsigned cc = cnt < (unsigned)SEGCAP ? cnt : (unsigned)SEGCAP;
        u64* key = sh;
        for (unsigned x = tid; x < cc; x += NTH) key[x] = g_cand[b][base + x];
        __syncthreads();
        for (unsigned x = tid; x < cc; x += NTH) {
            u64 me = key[x];
            unsigned rank = 0;
            for (unsigned y = 0; y < cc; y++) rank += (key[y] > me);
            unsigned p = base + rank;
            if (p >= PP) continue;
            unsigned idx = 0xFFFFFFFFu - (unsigned)(me & 0xFFFFFFFFull);
            float4 a = *(const float4*)(anchors + (size_t)idx * 4);
            float4 d = *(const float4*)(rpn_bbox + ((size_t)b * NN + idx) * 4);
            d.x *= 0.1f; d.y *= 0.1f; d.z *= 0.2f; d.w *= 0.2f;
            float h = a.z - a.x, w = a.w - a.y;
            float cy = a.x + 0.5f * h, cx = a.y + 0.5f * w;
            cy = cy + d.x * h;
            cx = cx + d.y * w;
            h = h * expf(d.z);
            w = w * expf(d.w);
            float y1 = cy - 0.5f * h, x1 = cx - 0.5f * w;
            float y2 = cy + 0.5f * h, x2 = cx + 0.5f * w;
            y1 = fminf(fmaxf(y1, 0.f), 1024.f);
            x1 = fminf(fmaxf(x1, 0.f), 1024.f);
            y2 = fminf(fmaxf(y2, 0.f), 1024.f);
            x2 = fminf(fmaxf(x2, 0.f), 1024.f);
            const float inv = 1.0f / 1024.0f;
            float4 o = make_float4(y1 * inv, x1 * inv, y2 * inv, x2 * inv);
            g_boxes[b][p] = o;
            g_area[b][p] = (o.z - o.x) * (o.w - o.y);
        }
        __syncthreads();
    }
    gbar(4);

    // ---- phase 5a: mask tiles for the speculative window (ib<=jb<BLK1) ----
    {
        float4* bj = (float4*)sh;
        float*  aj = (float*)(bj + 64);
        const int NIBG1 = (BLK1 + 15) / 16;           // 3
        const int PER_B = BLK1 * NIBG1;               // 120
        for (int st = cta; st < BB * PER_B; st += NCTA) {
            int b = st / PER_B;
            int r = st % PER_B;
            int jb = r / NIBG1, ibg = r % NIBG1;
            if (jb < ibg * 16) continue;
            mask_tile(b, ibg * 16 + (tid >> 6), jb, tid, bj, aj);
        }
    }
    gbar(5);

    // ---- phase 6a: speculative NMS over blocks [0, BLK1) ----
    if (cta < BB) {
        int b = cta;
        u64* s_diag = sh;
        u64* s_rownz = sh + DPAD;
        __shared__ u64 s_pre, s_kept;
        __shared__ unsigned s_nz[2];
        __shared__ int s_base, s_prev, s_stop;

        float4* ob = (float4*)(out + (size_t)b * NP * 4);
        for (int x = tid; x < NP; x += NTH) ob[x] = make_float4(0.f, 0.f, 0.f, 0.f);
        for (int x = tid; x < BLK1 * 64; x += NTH) s_diag[x] = g_diag[b][x];
        for (int x = tid; x < NW; x += NTH) s_rownz[x] = g_rownz[b][x];

        u64 acc = 0ull;
        if (tid == 0) { s_base = 0; s_stop = 0; }
        __syncthreads();

        for (int blk = 0; blk < BLK1; blk++) {
            if (tid < 64) {
                u64 d = s_diag[blk * 64 + tid];
                unsigned bal = __ballot_sync(0xffffffffu, d != 0ull);
                if ((tid & 31) == 0) s_nz[tid >> 5] = bal;
            }
            if (tid == blk) s_pre = acc;
            __syncthreads();

            if (tid == 0) {
                u64 jm = (u64)s_nz[0] | ((u64)s_nz[1] << 32);
                u64 alive = ~s_pre;
                while (jm) {
                    int j = __ffsll((long long)jm) - 1; jm &= jm - 1;
                    if ((alive >> j) & 1ull) alive &= ~s_diag[blk * 64 + j];
                }
                int cnt = __popcll(alive);
                int rem = NP - s_base;
                while (cnt > rem) {
                    alive &= ~(1ull << (63 - __clzll((long long)alive)));
                    cnt--;
                }
                s_kept = alive;
                g_keptmask[b][blk] = alive;
                s_prev = s_base;
                s_base += cnt;
                if (s_base >= NP) s_stop = 1;
            }
            __syncthreads();

            u64 km = s_kept;
            if (tid < 64 && ((km >> tid) & 1ull)) {
                u64 lowmask = (tid == 0) ? 0ull : (km & ((1ull << tid) - 1ull));
                ob[s_prev + __popcll(lowmask)] = g_boxes[b][blk * 64 + tid];
            }
            if (tid < BLK1 && tid > blk) {            // only columns < BLK1 are valid
                u64 nz = s_rownz[blk] & km;
                while (nz) {
                    int j = __ffsll((long long)nz) - 1; nz &= nz - 1;
                    acc |= g_supp[b][blk * 64 + j][tid];
                }
            }
            if (s_stop) break;
        }
        __syncthreads();
        if (tid < NW) g_removed[b][tid] = acc;        // tid>=BLK1 words are 0 (placeholder)
        if (tid == 0) { g_done[b] = s_stop; g_base[b] = s_base; }
    }
    gbar(6);

    // ---- all-done check (uniform across CTAs) ----
    {
        __shared__ int s_alldone;
        if (tid == 0)
            s_alldone = g_done[0] & g_done[1] & g_done[2] & g_done[3];
        __syncthreads();
        if (s_alldone) return;                        // common case
    }

    // ---- phase 7: remaining mask tiles (jb >= BLK1, ib <= jb) ----
    {
        float4* bj = (float4*)sh;
        float*  aj = (float*)(bj + 64);
        const int NIBG = (NW + 15) / 16;              // 6
        const int PER_B = (NW - BLK1) * NIBG;         // 324
        for (int st = cta; st < BB * PER_B; st += NCTA) {
            int b = st / PER_B;
            int r = st % PER_B;
            int jb = BLK1 + r / NIBG, ibg = r % NIBG;
            if (jb < ibg * 16) continue;
            mask_tile(b, ibg * 16 + (tid >> 6), jb, tid, bj, aj);
        }
    }
    gbar(7);
    if (cta >= BB) return;

    // ---- phase 8: NMS continuation over blocks [BLK1, NW) ----
    {
        int b = cta;
        u64* s_diag = sh;
        u64* s_rownz = sh + DPAD;
        __shared__ u64 s_pre, s_kept;
        __shared__ unsigned s_nz[2];
        __shared__ int s_base, s_prev, s_stop;

        float4* ob = (float4*)(out + (size_t)b * NP * 4);
        for (int x = tid; x < DPAD; x += NTH)
            s_diag[x] = (x < PP) ? g_diag[b][x] : 0ull;
        for (int x = tid; x < NW; x += NTH) s_rownz[x] = g_rownz[b][x];
        if (tid == 0) { s_base = g_base[b]; s_stop = g_done[b]; }
        __syncthreads();

        u64 acc = (tid < NW) ? g_removed[b][tid] : 0ull;
        if (tid >= BLK1 && tid < NW) {                // reconstruct high words
            for (int blk = 0; blk < BLK1; blk++) {
                u64 nz = s_rownz[blk] & g_keptmask[b][blk];
                while (nz) {
                    int j = __ffsll((long long)nz) - 1; nz &= nz - 1;
                    acc |= g_supp[b][blk * 64 + j][tid];
                }
            }
        }
        __syncthreads();

        for (int blk = BLK1; blk < NW && !s_stop; blk++) {
            if (tid < 64) {
                u64 d = s_diag[blk * 64 + tid];
                unsigned bal = __ballot_sync(0xffffffffu, d != 0ull);
                if ((tid & 31) == 0) s_nz[tid >> 5] = bal;
            }
            if (tid == blk) s_pre = acc;
            __syncthreads();

            if (tid == 0) {
                u64 jm = (u64)s_nz[0] | ((u64)s_nz[1] << 32);
                u64 alive = ~s_pre;
                if (blk == NW - 1) alive &= (1ull << (PP - (NW - 1) * 64)) - 1ull;
                while (jm) {
                    int j = __ffsll((long long)jm) - 1; jm &= jm - 1;
                    if ((alive >> j) & 1ull) alive &= ~s_diag[blk * 64 + j];
                }
                int cnt = __popcll(alive);
                int rem = NP - s_base;
                while (cnt > rem) {
                    alive &= ~(1ull << (63 - __clzll((long long)alive)));
                    cnt--;
                }
                s_kept = alive;
                s_prev = s_base;
                s_base += cnt;
                if (s_base >= NP) s_stop = 1;
            }
            __syncthreads();

            u64 km = s_kept;
            if (tid < 64 && ((km >> tid) & 1ull)) {
                u64 lowmask = (tid == 0) ? 0ull : (km & ((1ull << tid) - 1ull));
                ob[s_prev + __popcll(lowmask)] = g_boxes[b][blk * 64 + tid];
            }
            if (tid < NW && tid > blk) {
                u64 nz = s_rownz[blk] & km;
                while (nz) {
                    int j = __ffsll((long long)nz) - 1; nz &= nz - 1;
                    acc |= g_supp[b][blk * 64 + j][tid];
                }
            }
            __syncthreads();
        }
    }
}

// ---------------- launch ----------------
extern "C" void kernel_launch(void* const* d_in, const int* in_sizes, int n_in,
                              void* d_out, int out_size) {
    const float* rpn_class = (const float*)d_in[0];
    const float* rpn_bbox  = (const float*)d_in[1];
    const float* anchors   = (const float*)d_in[2];
    float* out = (float*)d_out;

    int smem = 131072;
    cudaFuncSetAttribute(k_all, cudaFuncAttributeMaxDynamicSharedMemorySize, smem);
    k_all<<<NCTA, NTH, smem>>>(rpn_class, rpn_bbox, anchors, out);
}